// round 13
// baseline (speedup 1.0000x reference)
#include <cuda_runtime.h>
#include <cuda_fp16.h>
#include <cstdint>

// Problem constants
#define T_STEPS 4
#define BATCH   32
#define CH      384
#define HW      196
#define HEADS   8
#define DH      48
#define CHW     (CH*HW)          // 75264
#define BCHW    (BATCH*CHW)      // 2408448
#define TOTAL   (T_STEPS*BCHW)   // 9633792
#define NTOT    (T_STEPS*BATCH*HW) // 25088 (= 196 * 128 exactly)

// Scratch (static device globals -- allocation-guard safe)
__device__ float  g_qbn[TOTAL];
__device__ float  g_kbn[TOTAL];
__device__ __half g_yhf[TOTAL];    // proj input, [n][c] row-major, exact 0/1
__device__ __half g_pw0[CH*CH];    // proj_w 2-way fp16 split
__device__ __half g_pw1[CH*CH];
__device__ __half g_qw0[CH*CH];    // q_w split
__device__ __half g_qw1[CH*CH];
__device__ __half g_kw0[CH*CH];    // k_w split
__device__ __half g_kw1[CH*CH];
__device__ __half g_x0[TOTAL];     // X 2-way fp16 split, [n][k] layout
__device__ __half g_x1[TOTAL];

// Column permutation: n = (b*HW + hw)*4 + t  -> groups of 4 = one pixel's T.
__device__ __forceinline__ int col_offset(int n) {
    int t   = n & 3;
    int bhw = n >> 2;
    int b   = bhw / HW;
    int hw  = bhw - b * HW;
    return t * BCHW + b * CHW + hw;     // offset without channel term
}

__device__ __forceinline__ uint32_t smem_u32(const void* p) {
    uint32_t a;
    asm("{ .reg .u64 t; cvta.to.shared.u64 t, %1; cvt.u32.u64 %0, t; }"
        : "=r"(a) : "l"(p));
    return a;
}

#define MMA16816(CP, A0, A1, A2, A3, B0, B1)                                    \
    asm volatile(                                                               \
        "mma.sync.aligned.m16n8k16.row.col.f32.f16.f16.f32 "                    \
        "{%0,%1,%2,%3}, {%4,%5,%6,%7}, {%8,%9}, {%0,%1,%2,%3};"                 \
        : "+f"((CP)[0]), "+f"((CP)[1]), "+f"((CP)[2]), "+f"((CP)[3])            \
        : "r"(A0), "r"(A1), "r"(A2), "r"(A3), "r"(B0), "r"(B1))

#define LDMX4(R0, R1, R2, R3, AD)                                               \
    asm volatile("ldmatrix.sync.aligned.m8n8.x4.shared.b16 {%0,%1,%2,%3}, [%4];"\
        : "=r"(R0), "=r"(R1), "=r"(R2), "=r"(R3) : "r"(AD))

// ===========================================================================
// weight 2-way fp16 split (~22 mantissa bits; residual <= 2^-25 abs)
// ===========================================================================
__global__ void wsplit2_kernel(const float* __restrict__ w,
                               __half* __restrict__ o0,
                               __half* __restrict__ o1)
{
    int i = blockIdx.x * blockDim.x + threadIdx.x;
    if (i >= CH * CH) return;
    float v = w[i];
    __half h0 = __float2half_rn(v);
    __half h1 = __float2half_rn(v - __half2float(h0));
    o0[i] = h0; o1[i] = h1;
}

// ===========================================================================
// X transpose + 2-way fp16 split:  X[t][b][c][hw] -> planes[n][c],
// n = (b*HW+hw)*4 + t
// ===========================================================================
__global__ void __launch_bounds__(256) xsplit_kernel(const float* __restrict__ X)
{
    __shared__ float tile[32][33];
    const int tb = blockIdx.x;           // t*BATCH + b
    const int t  = tb >> 5;
    const int b  = tb & 31;
    const int c0 = blockIdx.y * 32;
    const int tx = threadIdx.x, ty = threadIdx.y;

#pragma unroll 1
    for (int hw0 = 0; hw0 < HW; hw0 += 32) {
        __syncthreads();
#pragma unroll
        for (int i = 0; i < 4; i++) {
            int c  = c0 + ty + i * 8;
            int hw = hw0 + tx;
            tile[ty + i * 8][tx] = (hw < HW) ? X[tb * CHW + c * HW + hw] : 0.f;
        }
        __syncthreads();
#pragma unroll
        for (int i = 0; i < 4; i++) {
            int hw = hw0 + ty + i * 8;
            if (hw < HW) {
                float v = tile[tx][ty + i * 8];
                __half h0 = __float2half_rn(v);
                __half h1 = __float2half_rn(v - __half2float(h0));
                size_t o = ((size_t)(b * HW + hw) * 4 + t) * CH + c0 + tx;
                g_x0[o] = h0; g_x1[o] = h1;
            }
        }
    }
}

// ===========================================================================
// Q/K GEMM via 3-term fp16-split mma.sync (proven R10 config):
//   D = w0@x0 + w1@x0 + w0@x1
// CTA tile 128m x 128n, KC=32, 8 warps (4m x 2n), warp tile 32x64.
// ===========================================================================
#define KC      32
#define PITCH   40

__global__ void __launch_bounds__(256, 2) qk_mma_kernel(
    const __half* __restrict__ w0,
    const __half* __restrict__ w1,
    const float* __restrict__ gamma, const float* __restrict__ beta,
    const float* __restrict__ mean,  const float* __restrict__ var,
    float* __restrict__ out)
{
    __shared__ __half sA[2][128][PITCH];
    __shared__ __half sB[2][128][PITCH];
    __shared__ int colOff[128];

    const int tid  = threadIdx.x;
    const int wid  = tid >> 5;
    const int lane = tid & 31;
    const int mbase = blockIdx.y * 128;
    const int nbase = blockIdx.x * 128;

    if (tid < 128) colOff[tid] = col_offset(nbase + tid);

    const int wm = (wid & 3) * 32;
    const int wn = (wid >> 2) * 64;

    const int a_r  = (lane & 7) + ((lane >> 3) & 1) * 8;
    const int a_kc = (lane >> 4) * 8;
    const int b_r  = (lane & 7) + (lane >> 4) * 8;
    const int b_kc = ((lane >> 3) & 1) * 8;

    const __half* ga[2] = { w0 + (size_t)mbase * CH, w1 + (size_t)mbase * CH };
    const __half* gb[2] = { g_x0 + (size_t)nbase * CH, g_x1 + (size_t)nbase * CH };

    float acc[2][8][4];
#pragma unroll
    for (int mt = 0; mt < 2; mt++)
#pragma unroll
        for (int nt = 0; nt < 8; nt++)
#pragma unroll
            for (int r = 0; r < 4; r++) acc[mt][nt][r] = 0.f;

    const int l_row = tid >> 2;
    const int l_q   = (tid & 3) * 8;

#pragma unroll 1
    for (int kc = 0; kc < CH / KC; kc++) {
        const int kbase = kc * KC;
        __syncthreads();
#pragma unroll
        for (int r2 = 0; r2 < 2; r2++) {
            const int row = l_row + r2 * 64;
#pragma unroll
            for (int p = 0; p < 2; p++) {
                *reinterpret_cast<uint4*>(&sA[p][row][l_q]) =
                    *reinterpret_cast<const uint4*>(ga[p] + (size_t)row * CH + kbase + l_q);
                *reinterpret_cast<uint4*>(&sB[p][row][l_q]) =
                    *reinterpret_cast<const uint4*>(gb[p] + (size_t)row * CH + kbase + l_q);
            }
        }
        __syncthreads();

#pragma unroll
        for (int kk = 0; kk < 2; kk++) {
            const int k0 = kk * 16;
            uint32_t a[2][2][4];
#pragma unroll
            for (int p = 0; p < 2; p++)
#pragma unroll
                for (int mt = 0; mt < 2; mt++) {
                    uint32_t ad = smem_u32(&sA[p][wm + mt * 16 + a_r][k0 + a_kc]);
                    LDMX4(a[p][mt][0], a[p][mt][1], a[p][mt][2], a[p][mt][3], ad);
                }
#pragma unroll
            for (int nt2 = 0; nt2 < 4; nt2++) {
                uint32_t b[2][4];
#pragma unroll
                for (int p = 0; p < 2; p++) {
                    uint32_t bd = smem_u32(&sB[p][wn + nt2 * 16 + b_r][k0 + b_kc]);
                    LDMX4(b[p][0], b[p][1], b[p][2], b[p][3], bd);
                }
#define QK_PAIR(I, J)                                                           \
                _Pragma("unroll")                                               \
                for (int mt = 0; mt < 2; mt++) {                                \
                    MMA16816(acc[mt][nt2 * 2],                                  \
                             a[I][mt][0], a[I][mt][1], a[I][mt][2], a[I][mt][3],\
                             b[J][0], b[J][1]);                                 \
                    MMA16816(acc[mt][nt2 * 2 + 1],                              \
                             a[I][mt][0], a[I][mt][1], a[I][mt][2], a[I][mt][3],\
                             b[J][2], b[J][3]);                                 \
                }
                QK_PAIR(0, 0)
                QK_PAIR(1, 0)
                QK_PAIR(0, 1)
#undef QK_PAIR
            }
        }
    }

    // Epilogue: BN then scatter store (NCHW layout; colOff includes t term)
#pragma unroll
    for (int mt = 0; mt < 2; mt++) {
        int oa = mbase + wm + mt * 16 + (lane >> 2);
        int ob = oa + 8;
        float inva = gamma[oa] / sqrtf(var[oa] + 1e-5f);
        float sha  = beta[oa] - mean[oa] * inva;
        float invb = gamma[ob] / sqrtf(var[ob] + 1e-5f);
        float shb  = beta[ob] - mean[ob] * invb;
#pragma unroll
        for (int nt = 0; nt < 8; nt++) {
            int n  = wn + nt * 8 + (lane & 3) * 2;
            int c0 = colOff[n], c1 = colOff[n + 1];
            const float* c = acc[mt][nt];
            out[c0 + oa * HW] = c[0] * inva + sha;
            out[c1 + oa * HW] = c[1] * inva + sha;
            out[c0 + ob * HW] = c[2] * invb + shb;
            out[c1 + ob * HW] = c[3] * invb + shb;
        }
    }
}

// ===========================================================================
// LIF on q,k + per-head sum-pool attention gate -> y as fp16 [n][c] row-major
// (n in the permuted (b,hw,t) order)
// ===========================================================================
__device__ __forceinline__ uint32_t pk2h(uint32_t m) {
    return ((m & 1u) ? 0x3C00u : 0u) | ((m & 2u) ? 0x3C000000u : 0u);
}

__global__ void __launch_bounds__(896) lif_attn_kernel()
{
    __shared__ float    s_qs[4][224][4];
    __shared__ uint32_t s_kb[4][224][4];
    __shared__ uint32_t s_m[224][4][2];

    const int bh   = blockIdx.x;
    const int b    = bh >> 3;
    const int head = bh & 7;
    const int hw   = threadIdx.x;
    const int dg   = threadIdx.y;
    const bool act = hw < HW;

    const int cb    = head * DH + dg * 12;
    const int base0 = b * CHW + cb * HW + hw;

    float    qs[4] = {0.f, 0.f, 0.f, 0.f};
    uint32_t kb[4] = {0u, 0u, 0u, 0u};

    if (act) {
#pragma unroll 1
        for (int d = 0; d < 12; d++) {
            int idx = base0 + d * HW;
            float vq = 0.f, vk = 0.f;
#pragma unroll
            for (int t = 0; t < 4; t++) {
                float xq = g_qbn[idx + t * BCHW];
                float xk = g_kbn[idx + t * BCHW];
                float hq = vq + (xq - vq) * 0.5f;
                float hk = vk + (xk - vk) * 0.5f;
                bool sq = (hq - 1.0f) >= 0.0f;
                bool sk = (hk - 1.0f) >= 0.0f;
                vq = sq ? 0.f : hq;
                vk = sk ? 0.f : hk;
                if (sq) qs[t] += 1.0f;
                if (sk) kb[t] |= (1u << d);
            }
        }
    }
#pragma unroll
    for (int t = 0; t < 4; t++) {
        s_qs[dg][hw][t] = qs[t];
        s_kb[dg][hw][t] = kb[t];
    }
    __syncthreads();

    if (dg == 0 && act) {
        float va = 0.f;
#pragma unroll
        for (int t = 0; t < 4; t++) {
            float q = qs[t] + s_qs[1][hw][t] + s_qs[2][hw][t] + s_qs[3][hw][t];
            uint32_t m0 = kb[t] | (s_kb[1][hw][t] << 12);
            uint32_t m1 = s_kb[2][hw][t] | (s_kb[3][hw][t] << 12);
            float h = va + (q - va) * 0.5f;
            bool s  = (h - 0.5f) >= 0.0f;
            va = s ? 0.f : h;
            s_m[hw][t][0] = s ? m0 : 0u;
            s_m[hw][t][1] = s ? m1 : 0u;
        }
    }
    __syncthreads();

    const int tidl = dg * 224 + hw;
#pragma unroll 1
    for (int l = tidl; l < HW * 4 * 6; l += 896) {
        int g  = l % 6;
        int r  = l / 6;
        int whw = r % HW;
        int t   = r / HW;
        uint32_t mask = s_m[whw][t][g >= 3 ? 1 : 0];
        uint32_t bits = mask >> ((g >= 3 ? g - 3 : g) * 8);
        uint4 v;
        v.x = pk2h(bits);
        v.y = pk2h(bits >> 2);
        v.z = pk2h(bits >> 4);
        v.w = pk2h(bits >> 6);
        size_t n = (size_t)(b * HW + whw) * 4 + t;        // permuted column order
        uint4* dst = reinterpret_cast<uint4*>(g_yhf + n * CH + head * DH);
        dst[g] = v;
    }
}

// ===========================================================================
// proj GEMM via 2-term fp16-split mma.sync + FUSED final LIF.
// Columns ordered (b,hw,t): adjacent lanes hold t{0,1}/t{2,3} of one pixel;
// one shfl_xor(1) carries the membrane potential across the lane pair.
// Writes 0/1 spikes directly to d_out.
// ===========================================================================
__device__ __forceinline__ void lif_pair(int lane, float z0, float z1,
                                         float& s0, float& s1)
{
    // chain assuming vstart = 0 (correct for even lane = t0,t1)
    float h0 = z0 * 0.5f;
    bool  a0 = h0 >= 1.0f;
    float v  = a0 ? 0.f : h0;
    float h1 = v + (z1 - v) * 0.5f;
    bool  a1 = h1 >= 1.0f;
    float v1 = a1 ? 0.f : h1;
    float vin = __shfl_xor_sync(0xffffffffu, v1, 1);
    if (lane & 1) {       // odd lane: redo chain with carried-in membrane
        h0 = vin + (z0 - vin) * 0.5f;
        a0 = h0 >= 1.0f;
        v  = a0 ? 0.f : h0;
        h1 = v + (z1 - v) * 0.5f;
        a1 = h1 >= 1.0f;
    }
    s0 = a0 ? 1.f : 0.f;
    s1 = a1 ? 1.f : 0.f;
}

__global__ void __launch_bounds__(256, 2) proj_mma_kernel(
    const float* __restrict__ gamma, const float* __restrict__ beta,
    const float* __restrict__ mean,  const float* __restrict__ var,
    const float* __restrict__ bias,  float* __restrict__ out)
{
    __shared__ __half sA[2][128][PITCH];
    __shared__ __half sB[128][PITCH];
    __shared__ int colOff[128];

    const int tid  = threadIdx.x;
    const int wid  = tid >> 5;
    const int lane = tid & 31;
    const int mbase = blockIdx.y * 128;
    const int nbase = blockIdx.x * 128;

    if (tid < 128) colOff[tid] = col_offset(nbase + tid);

    const int wm = (wid & 3) * 32;
    const int wn = (wid >> 2) * 64;

    const int a_r  = (lane & 7) + ((lane >> 3) & 1) * 8;
    const int a_kc = (lane >> 4) * 8;
    const int b_r  = (lane & 7) + (lane >> 4) * 8;
    const int b_kc = ((lane >> 3) & 1) * 8;

    const __half* ga[2] = { g_pw0 + (size_t)mbase * CH, g_pw1 + (size_t)mbase * CH };
    const __half* gy = g_yhf + (size_t)nbase * CH;

    float acc[2][8][4];
#pragma unroll
    for (int mt = 0; mt < 2; mt++)
#pragma unroll
        for (int nt = 0; nt < 8; nt++)
#pragma unroll
            for (int r = 0; r < 4; r++) acc[mt][nt][r] = 0.f;

    const int l_row = tid >> 2;
    const int l_q   = (tid & 3) * 8;

#pragma unroll 1
    for (int kc = 0; kc < CH / KC; kc++) {
        const int kbase = kc * KC;
        __syncthreads();
#pragma unroll
        for (int r2 = 0; r2 < 2; r2++) {
            const int row = l_row + r2 * 64;
#pragma unroll
            for (int p = 0; p < 2; p++)
                *reinterpret_cast<uint4*>(&sA[p][row][l_q]) =
                    *reinterpret_cast<const uint4*>(ga[p] + (size_t)row * CH + kbase + l_q);
            *reinterpret_cast<uint4*>(&sB[row][l_q]) =
                *reinterpret_cast<const uint4*>(gy + (size_t)row * CH + kbase + l_q);
        }
        __syncthreads();

#pragma unroll
        for (int kk = 0; kk < 2; kk++) {
            const int k0 = kk * 16;
            uint32_t a[2][2][4];
#pragma unroll
            for (int p = 0; p < 2; p++)
#pragma unroll
                for (int mt = 0; mt < 2; mt++) {
                    uint32_t ad = smem_u32(&sA[p][wm + mt * 16 + a_r][k0 + a_kc]);
                    LDMX4(a[p][mt][0], a[p][mt][1], a[p][mt][2], a[p][mt][3], ad);
                }
#pragma unroll
            for (int nt2 = 0; nt2 < 4; nt2++) {
                uint32_t b0, b1, b2, b3;
                uint32_t bd = smem_u32(&sB[wn + nt2 * 16 + b_r][k0 + b_kc]);
                LDMX4(b0, b1, b2, b3, bd);
#pragma unroll
                for (int p = 0; p < 2; p++)
#pragma unroll
                    for (int mt = 0; mt < 2; mt++) {
                        MMA16816(acc[mt][nt2 * 2],
                                 a[p][mt][0], a[p][mt][1], a[p][mt][2], a[p][mt][3],
                                 b0, b1);
                        MMA16816(acc[mt][nt2 * 2 + 1],
                                 a[p][mt][0], a[p][mt][1], a[p][mt][2], a[p][mt][3],
                                 b2, b3);
                    }
            }
        }
    }

    // Epilogue: bias + BN -> fused LIF over T (shfl pair) -> spike store
#pragma unroll
    for (int mt = 0; mt < 2; mt++) {
        int oa = mbase + wm + mt * 16 + (lane >> 2);
        int ob = oa + 8;
        float inva = gamma[oa] / sqrtf(var[oa] + 1e-5f);
        float sha  = beta[oa] - mean[oa] * inva;
        float bva  = bias[oa];
        float invb = gamma[ob] / sqrtf(var[ob] + 1e-5f);
        float shb  = beta[ob] - mean[ob] * invb;
        float bvb  = bias[ob];
#pragma unroll
        for (int nt = 0; nt < 8; nt++) {
            int n  = wn + nt * 8 + (lane & 3) * 2;
            int c0 = colOff[n], c1 = colOff[n + 1];
            const float* c = acc[mt][nt];
            float za0 = (c[0] + bva) * inva + sha;
            float za1 = (c[1] + bva) * inva + sha;
            float zb0 = (c[2] + bvb) * invb + shb;
            float zb1 = (c[3] + bvb) * invb + shb;
            float sa0, sa1, sb0, sb1;
            lif_pair(lane, za0, za1, sa0, sa1);
            lif_pair(lane, zb0, zb1, sb0, sb1);
            out[c0 + oa * HW] = sa0;
            out[c1 + oa * HW] = sa1;
            out[c0 + ob * HW] = sb0;
            out[c1 + ob * HW] = sb1;
        }
    }
}

// ===========================================================================
extern "C" void kernel_launch(void* const* d_in, const int* in_sizes, int n_in,
                              void* d_out, int out_size)
{
    const float* x          = (const float*)d_in[0];
    const float* q_w        = (const float*)d_in[1];
    const float* q_gamma    = (const float*)d_in[2];
    const float* q_beta     = (const float*)d_in[3];
    const float* q_mean     = (const float*)d_in[4];
    const float* q_var      = (const float*)d_in[5];
    const float* k_w        = (const float*)d_in[6];
    const float* k_gamma    = (const float*)d_in[7];
    const float* k_beta     = (const float*)d_in[8];
    const float* k_mean     = (const float*)d_in[9];
    const float* k_var      = (const float*)d_in[10];
    const float* proj_w     = (const float*)d_in[11];
    const float* proj_b     = (const float*)d_in[12];
    const float* proj_gamma = (const float*)d_in[13];
    const float* proj_beta  = (const float*)d_in[14];
    const float* proj_mean  = (const float*)d_in[15];
    const float* proj_var   = (const float*)d_in[16];

    __half *qw0, *qw1, *kw0, *kw1, *pw0, *pw1;
    cudaGetSymbolAddress((void**)&qw0, g_qw0);
    cudaGetSymbolAddress((void**)&qw1, g_qw1);
    cudaGetSymbolAddress((void**)&kw0, g_kw0);
    cudaGetSymbolAddress((void**)&kw1, g_kw1);
    cudaGetSymbolAddress((void**)&pw0, g_pw0);
    cudaGetSymbolAddress((void**)&pw1, g_pw1);
    float* qbn; float* kbn;
    cudaGetSymbolAddress((void**)&qbn, g_qbn);
    cudaGetSymbolAddress((void**)&kbn, g_kbn);

    dim3 ggrid(NTOT / 128, CH / 128);   // (196, 3)
    int wblocks = (CH * CH + 255) / 256;

    wsplit2_kernel<<<wblocks, 256>>>(q_w, qw0, qw1);
    wsplit2_kernel<<<wblocks, 256>>>(k_w, kw0, kw1);
    wsplit2_kernel<<<wblocks, 256>>>(proj_w, pw0, pw1);
    xsplit_kernel<<<dim3(T_STEPS * BATCH, CH / 32), dim3(32, 8)>>>(x);
    qk_mma_kernel<<<ggrid, 256>>>(qw0, qw1, q_gamma, q_beta, q_mean, q_var, qbn);
    qk_mma_kernel<<<ggrid, 256>>>(kw0, kw1, k_gamma, k_beta, k_mean, k_var, kbn);
    lif_attn_kernel<<<BATCH * HEADS, dim3(224, 4)>>>();
    proj_mma_kernel<<<ggrid, 256>>>(proj_gamma, proj_beta,
                                    proj_mean, proj_var, proj_b,
                                    (float*)d_out);
}

// round 14
// speedup vs baseline: 1.1134x; 1.1134x over previous
#include <cuda_runtime.h>
#include <cuda_fp16.h>
#include <cstdint>

// Problem constants
#define T_STEPS 4
#define BATCH   32
#define CH      384
#define HW      196
#define HEADS   8
#define DH      48
#define CHW     (CH*HW)          // 75264
#define BCHW    (BATCH*CHW)      // 2408448
#define TOTAL   (T_STEPS*BCHW)   // 9633792
#define NTOT    (T_STEPS*BATCH*HW) // 25088 (= 196 * 128 exactly)

// Scratch (static device globals -- allocation-guard safe)
__device__ float  g_qbn[TOTAL];
__device__ float  g_kbn[TOTAL];
__device__ __half g_yhf[TOTAL];    // proj input, [n][c] row-major (n permuted), 0/1
__device__ __half g_pw0[CH*CH];    // proj_w 2-way fp16 split
__device__ __half g_pw1[CH*CH];
__device__ __half g_qw0[CH*CH];    // q_w split
__device__ __half g_qw1[CH*CH];
__device__ __half g_kw0[CH*CH];    // k_w split
__device__ __half g_kw1[CH*CH];
__device__ __half g_x0[TOTAL];     // X 2-way fp16 split, [n][k] layout (qk order)
__device__ __half g_x1[TOTAL];

// proj column permutation: n = (b*HW + hw)*4 + t  (4 consecutive = one pixel's T)
__device__ __forceinline__ int proj_col_offset(int n) {
    int t   = n & 3;
    int bhw = n >> 2;
    int b   = bhw / HW;
    int hw  = bhw - b * HW;
    return t * BCHW + b * CHW + hw;     // offset without channel term
}

__device__ __forceinline__ uint32_t smem_u32(const void* p) {
    uint32_t a;
    asm("{ .reg .u64 t; cvta.to.shared.u64 t, %1; cvt.u32.u64 %0, t; }"
        : "=r"(a) : "l"(p));
    return a;
}

#define MMA16816(CP, A0, A1, A2, A3, B0, B1)                                    \
    asm volatile(                                                               \
        "mma.sync.aligned.m16n8k16.row.col.f32.f16.f16.f32 "                    \
        "{%0,%1,%2,%3}, {%4,%5,%6,%7}, {%8,%9}, {%0,%1,%2,%3};"                 \
        : "+f"((CP)[0]), "+f"((CP)[1]), "+f"((CP)[2]), "+f"((CP)[3])            \
        : "r"(A0), "r"(A1), "r"(A2), "r"(A3), "r"(B0), "r"(B1))

#define LDMX4(R0, R1, R2, R3, AD)                                               \
    asm volatile("ldmatrix.sync.aligned.m8n8.x4.shared.b16 {%0,%1,%2,%3}, [%4];"\
        : "=r"(R0), "=r"(R1), "=r"(R2), "=r"(R3) : "r"(AD))

// ===========================================================================
// weight 2-way fp16 split (~22 mantissa bits; residual <= 2^-25 abs)
// ===========================================================================
__global__ void wsplit2_kernel(const float* __restrict__ w,
                               __half* __restrict__ o0,
                               __half* __restrict__ o1)
{
    int i = blockIdx.x * blockDim.x + threadIdx.x;
    if (i >= CH * CH) return;
    float v = w[i];
    __half h0 = __float2half_rn(v);
    __half h1 = __float2half_rn(v - __half2float(h0));
    o0[i] = h0; o1[i] = h1;
}

// ===========================================================================
// X transpose + 2-way fp16 split:  X[tb][c][hw] -> planes[n][c],
// n = (t*BATCH+b)*HW + hw   (qk GEMM column order, as in R10)
// ===========================================================================
__global__ void __launch_bounds__(256) xsplit_kernel(const float* __restrict__ X)
{
    __shared__ float tile[32][33];
    const int tb = blockIdx.x;
    const int c0 = blockIdx.y * 32;
    const int tx = threadIdx.x, ty = threadIdx.y;

#pragma unroll 1
    for (int hw0 = 0; hw0 < HW; hw0 += 32) {
        __syncthreads();
#pragma unroll
        for (int i = 0; i < 4; i++) {
            int c  = c0 + ty + i * 8;
            int hw = hw0 + tx;
            tile[ty + i * 8][tx] = (hw < HW) ? X[tb * CHW + c * HW + hw] : 0.f;
        }
        __syncthreads();
#pragma unroll
        for (int i = 0; i < 4; i++) {
            int hw = hw0 + ty + i * 8;
            if (hw < HW) {
                float v = tile[tx][ty + i * 8];
                __half h0 = __float2half_rn(v);
                __half h1 = __float2half_rn(v - __half2float(h0));
                size_t o = (size_t)(tb * HW + hw) * CH + c0 + tx;
                g_x0[o] = h0; g_x1[o] = h1;
            }
        }
    }
}

// ===========================================================================
// Q/K GEMM via 3-term fp16-split mma.sync (EXACT R10 config; unpermuted cols)
//   D = w0@x0 + w1@x0 + w0@x1
// ===========================================================================
#define KC      32
#define PITCH   40

__global__ void __launch_bounds__(256, 2) qk_mma_kernel(
    const __half* __restrict__ w0,
    const __half* __restrict__ w1,
    const float* __restrict__ gamma, const float* __restrict__ beta,
    const float* __restrict__ mean,  const float* __restrict__ var,
    float* __restrict__ out)
{
    __shared__ __half sA[2][128][PITCH];
    __shared__ __half sB[2][128][PITCH];
    __shared__ int colOff[128];

    const int tid  = threadIdx.x;
    const int wid  = tid >> 5;
    const int lane = tid & 31;
    const int mbase = blockIdx.y * 128;
    const int nbase = blockIdx.x * 128;

    if (tid < 128) {
        int n  = nbase + tid;
        int tb = n / HW;
        colOff[tid] = tb * CHW + (n - tb * HW);
    }

    const int wm = (wid & 3) * 32;
    const int wn = (wid >> 2) * 64;

    const int a_r  = (lane & 7) + ((lane >> 3) & 1) * 8;
    const int a_kc = (lane >> 4) * 8;
    const int b_r  = (lane & 7) + (lane >> 4) * 8;
    const int b_kc = ((lane >> 3) & 1) * 8;

    const __half* ga[2] = { w0 + (size_t)mbase * CH, w1 + (size_t)mbase * CH };
    const __half* gb[2] = { g_x0 + (size_t)nbase * CH, g_x1 + (size_t)nbase * CH };

    float acc[2][8][4];
#pragma unroll
    for (int mt = 0; mt < 2; mt++)
#pragma unroll
        for (int nt = 0; nt < 8; nt++)
#pragma unroll
            for (int r = 0; r < 4; r++) acc[mt][nt][r] = 0.f;

    const int l_row = tid >> 2;
    const int l_q   = (tid & 3) * 8;

#pragma unroll 1
    for (int kc = 0; kc < CH / KC; kc++) {
        const int kbase = kc * KC;
        __syncthreads();
#pragma unroll
        for (int r2 = 0; r2 < 2; r2++) {
            const int row = l_row + r2 * 64;
#pragma unroll
            for (int p = 0; p < 2; p++) {
                *reinterpret_cast<uint4*>(&sA[p][row][l_q]) =
                    *reinterpret_cast<const uint4*>(ga[p] + (size_t)row * CH + kbase + l_q);
                *reinterpret_cast<uint4*>(&sB[p][row][l_q]) =
                    *reinterpret_cast<const uint4*>(gb[p] + (size_t)row * CH + kbase + l_q);
            }
        }
        __syncthreads();

#pragma unroll
        for (int kk = 0; kk < 2; kk++) {
            const int k0 = kk * 16;
            uint32_t a[2][2][4];
#pragma unroll
            for (int p = 0; p < 2; p++)
#pragma unroll
                for (int mt = 0; mt < 2; mt++) {
                    uint32_t ad = smem_u32(&sA[p][wm + mt * 16 + a_r][k0 + a_kc]);
                    LDMX4(a[p][mt][0], a[p][mt][1], a[p][mt][2], a[p][mt][3], ad);
                }
#pragma unroll
            for (int nt2 = 0; nt2 < 4; nt2++) {
                uint32_t b[2][4];
#pragma unroll
                for (int p = 0; p < 2; p++) {
                    uint32_t bd = smem_u32(&sB[p][wn + nt2 * 16 + b_r][k0 + b_kc]);
                    LDMX4(b[p][0], b[p][1], b[p][2], b[p][3], bd);
                }
#define QK_PAIR(I, J)                                                           \
                _Pragma("unroll")                                               \
                for (int mt = 0; mt < 2; mt++) {                                \
                    MMA16816(acc[mt][nt2 * 2],                                  \
                             a[I][mt][0], a[I][mt][1], a[I][mt][2], a[I][mt][3],\
                             b[J][0], b[J][1]);                                 \
                    MMA16816(acc[mt][nt2 * 2 + 1],                              \
                             a[I][mt][0], a[I][mt][1], a[I][mt][2], a[I][mt][3],\
                             b[J][2], b[J][3]);                                 \
                }
                QK_PAIR(0, 0)
                QK_PAIR(1, 0)
                QK_PAIR(0, 1)
#undef QK_PAIR
            }
        }
    }

    // Epilogue: BN then store (NCHW layout, coalesced pairs as in R10)
#pragma unroll
    for (int mt = 0; mt < 2; mt++) {
        int oa = mbase + wm + mt * 16 + (lane >> 2);
        int ob = oa + 8;
        float inva = gamma[oa] / sqrtf(var[oa] + 1e-5f);
        float sha  = beta[oa] - mean[oa] * inva;
        float invb = gamma[ob] / sqrtf(var[ob] + 1e-5f);
        float shb  = beta[ob] - mean[ob] * invb;
#pragma unroll
        for (int nt = 0; nt < 8; nt++) {
            int n  = wn + nt * 8 + (lane & 3) * 2;
            int c0 = colOff[n], c1 = colOff[n + 1];
            const float* c = acc[mt][nt];
            out[c0 + oa * HW] = c[0] * inva + sha;
            out[c1 + oa * HW] = c[1] * inva + sha;
            out[c0 + ob * HW] = c[2] * invb + shb;
            out[c1 + ob * HW] = c[3] * invb + shb;
        }
    }
}

// ===========================================================================
// LIF on q,k + per-head sum-pool attention gate -> y as fp16 [n][c] row-major
// with n in proj's permuted (b,hw,t) order.
// ===========================================================================
__device__ __forceinline__ uint32_t pk2h(uint32_t m) {
    return ((m & 1u) ? 0x3C00u : 0u) | ((m & 2u) ? 0x3C000000u : 0u);
}

__global__ void __launch_bounds__(896) lif_attn_kernel()
{
    __shared__ float    s_qs[4][224][4];
    __shared__ uint32_t s_kb[4][224][4];
    __shared__ uint32_t s_m[224][4][2];

    const int bh   = blockIdx.x;
    const int b    = bh >> 3;
    const int head = bh & 7;
    const int hw   = threadIdx.x;
    const int dg   = threadIdx.y;
    const bool act = hw < HW;

    const int cb    = head * DH + dg * 12;
    const int base0 = b * CHW + cb * HW + hw;

    float    qs[4] = {0.f, 0.f, 0.f, 0.f};
    uint32_t kb[4] = {0u, 0u, 0u, 0u};

    if (act) {
#pragma unroll 1
        for (int d = 0; d < 12; d++) {
            int idx = base0 + d * HW;
            float vq = 0.f, vk = 0.f;
#pragma unroll
            for (int t = 0; t < 4; t++) {
                float xq = g_qbn[idx + t * BCHW];
                float xk = g_kbn[idx + t * BCHW];
                float hq = vq + (xq - vq) * 0.5f;
                float hk = vk + (xk - vk) * 0.5f;
                bool sq = (hq - 1.0f) >= 0.0f;
                bool sk = (hk - 1.0f) >= 0.0f;
                vq = sq ? 0.f : hq;
                vk = sk ? 0.f : hk;
                if (sq) qs[t] += 1.0f;
                if (sk) kb[t] |= (1u << d);
            }
        }
    }
#pragma unroll
    for (int t = 0; t < 4; t++) {
        s_qs[dg][hw][t] = qs[t];
        s_kb[dg][hw][t] = kb[t];
    }
    __syncthreads();

    if (dg == 0 && act) {
        float va = 0.f;
#pragma unroll
        for (int t = 0; t < 4; t++) {
            float q = qs[t] + s_qs[1][hw][t] + s_qs[2][hw][t] + s_qs[3][hw][t];
            uint32_t m0 = kb[t] | (s_kb[1][hw][t] << 12);
            uint32_t m1 = s_kb[2][hw][t] | (s_kb[3][hw][t] << 12);
            float h = va + (q - va) * 0.5f;
            bool s  = (h - 0.5f) >= 0.0f;
            va = s ? 0.f : h;
            s_m[hw][t][0] = s ? m0 : 0u;
            s_m[hw][t][1] = s ? m1 : 0u;
        }
    }
    __syncthreads();

    const int tidl = dg * 224 + hw;
#pragma unroll 1
    for (int l = tidl; l < HW * 4 * 6; l += 896) {
        int g  = l % 6;
        int r  = l / 6;
        int whw = r % HW;
        int t   = r / HW;
        uint32_t mask = s_m[whw][t][g >= 3 ? 1 : 0];
        uint32_t bits = mask >> ((g >= 3 ? g - 3 : g) * 8);
        uint4 v;
        v.x = pk2h(bits);
        v.y = pk2h(bits >> 2);
        v.z = pk2h(bits >> 4);
        v.w = pk2h(bits >> 6);
        size_t n = (size_t)(b * HW + whw) * 4 + t;        // permuted column order
        uint4* dst = reinterpret_cast<uint4*>(g_yhf + n * CH + head * DH);
        dst[g] = v;
    }
}

// ===========================================================================
// proj GEMM (2-term fp16 split) + FUSED final LIF (permuted columns).
// Adjacent lanes hold t{0,1}/t{2,3} of one pixel; one shfl_xor(1) carries
// the membrane. Spikes staged as BYTES in smem, then stored plane-major:
// per (channel,t), 32 threads write 32 consecutive-hw floats (coalesced).
// ===========================================================================
__device__ __forceinline__ void lif_pair(int lane, float z0, float z1,
                                         float& s0, float& s1)
{
    float h0 = z0 * 0.5f;               // vstart = 0 (even lane = t0,t1)
    bool  a0 = h0 >= 1.0f;
    float v  = a0 ? 0.f : h0;
    float h1 = v + (z1 - v) * 0.5f;
    bool  a1 = h1 >= 1.0f;
    float v1 = a1 ? 0.f : h1;
    float vin = __shfl_xor_sync(0xffffffffu, v1, 1);
    if (lane & 1) {                     // odd lane: redo with carried membrane
        h0 = vin + (z0 - vin) * 0.5f;
        a0 = h0 >= 1.0f;
        v  = a0 ? 0.f : h0;
        h1 = v + (z1 - v) * 0.5f;
        a1 = h1 >= 1.0f;
    }
    s0 = a0 ? 1.f : 0.f;
    s1 = a1 ? 1.f : 0.f;
}

#define SBP 132   // sbuf row pitch (bytes)

__global__ void __launch_bounds__(256, 2) proj_mma_kernel(
    const float* __restrict__ gamma, const float* __restrict__ beta,
    const float* __restrict__ mean,  const float* __restrict__ var,
    const float* __restrict__ bias,  float* __restrict__ out)
{
    __shared__ __half sA[2][128][PITCH];
    __shared__ __half sB[128][PITCH];
    __shared__ unsigned char sbuf[128][SBP];   // [local n][local m] spikes
    __shared__ int colOff[128];

    const int tid  = threadIdx.x;
    const int wid  = tid >> 5;
    const int lane = tid & 31;
    const int mbase = blockIdx.y * 128;
    const int nbase = blockIdx.x * 128;

    if (tid < 128) colOff[tid] = proj_col_offset(nbase + tid);

    const int wm = (wid & 3) * 32;
    const int wn = (wid >> 2) * 64;

    const int a_r  = (lane & 7) + ((lane >> 3) & 1) * 8;
    const int a_kc = (lane >> 4) * 8;
    const int b_r  = (lane & 7) + (lane >> 4) * 8;
    const int b_kc = ((lane >> 3) & 1) * 8;

    const __half* ga[2] = { g_pw0 + (size_t)mbase * CH, g_pw1 + (size_t)mbase * CH };
    const __half* gy = g_yhf + (size_t)nbase * CH;

    float acc[2][8][4];
#pragma unroll
    for (int mt = 0; mt < 2; mt++)
#pragma unroll
        for (int nt = 0; nt < 8; nt++)
#pragma unroll
            for (int r = 0; r < 4; r++) acc[mt][nt][r] = 0.f;

    const int l_row = tid >> 2;
    const int l_q   = (tid & 3) * 8;

#pragma unroll 1
    for (int kc = 0; kc < CH / KC; kc++) {
        const int kbase = kc * KC;
        __syncthreads();
#pragma unroll
        for (int r2 = 0; r2 < 2; r2++) {
            const int row = l_row + r2 * 64;
#pragma unroll
            for (int p = 0; p < 2; p++)
                *reinterpret_cast<uint4*>(&sA[p][row][l_q]) =
                    *reinterpret_cast<const uint4*>(ga[p] + (size_t)row * CH + kbase + l_q);
            *reinterpret_cast<uint4*>(&sB[row][l_q]) =
                *reinterpret_cast<const uint4*>(gy + (size_t)row * CH + kbase + l_q);
        }
        __syncthreads();

#pragma unroll
        for (int kk = 0; kk < 2; kk++) {
            const int k0 = kk * 16;
            uint32_t a[2][2][4];
#pragma unroll
            for (int p = 0; p < 2; p++)
#pragma unroll
                for (int mt = 0; mt < 2; mt++) {
                    uint32_t ad = smem_u32(&sA[p][wm + mt * 16 + a_r][k0 + a_kc]);
                    LDMX4(a[p][mt][0], a[p][mt][1], a[p][mt][2], a[p][mt][3], ad);
                }
#pragma unroll
            for (int nt2 = 0; nt2 < 4; nt2++) {
                uint32_t b0, b1, b2, b3;
                uint32_t bd = smem_u32(&sB[wn + nt2 * 16 + b_r][k0 + b_kc]);
                LDMX4(b0, b1, b2, b3, bd);
#pragma unroll
                for (int p = 0; p < 2; p++)
#pragma unroll
                    for (int mt = 0; mt < 2; mt++) {
                        MMA16816(acc[mt][nt2 * 2],
                                 a[p][mt][0], a[p][mt][1], a[p][mt][2], a[p][mt][3],
                                 b0, b1);
                        MMA16816(acc[mt][nt2 * 2 + 1],
                                 a[p][mt][0], a[p][mt][1], a[p][mt][2], a[p][mt][3],
                                 b2, b3);
                    }
            }
        }
    }

    // Epilogue 1: bias + BN -> fused LIF -> spike bytes into smem
    __syncthreads();     // sB reads done; safe to start sbuf stores too (disjoint)
#pragma unroll
    for (int mt = 0; mt < 2; mt++) {
        int ma = wm + mt * 16 + (lane >> 2);
        int mb = ma + 8;
        int oa = mbase + ma, ob = mbase + mb;
        float inva = gamma[oa] / sqrtf(var[oa] + 1e-5f);
        float sha  = beta[oa] - mean[oa] * inva;
        float bva  = bias[oa];
        float invb = gamma[ob] / sqrtf(var[ob] + 1e-5f);
        float shb  = beta[ob] - mean[ob] * invb;
        float bvb  = bias[ob];
#pragma unroll
        for (int nt = 0; nt < 8; nt++) {
            int n = wn + nt * 8 + (lane & 3) * 2;
            const float* c = acc[mt][nt];
            float za0 = (c[0] + bva) * inva + sha;
            float za1 = (c[1] + bva) * inva + sha;
            float zb0 = (c[2] + bvb) * invb + shb;
            float zb1 = (c[3] + bvb) * invb + shb;
            float sa0, sa1, sb0, sb1;
            lif_pair(lane, za0, za1, sa0, sa1);
            lif_pair(lane, zb0, zb1, sb0, sb1);
            sbuf[n][ma]     = (unsigned char)(sa0 != 0.f);
            sbuf[n + 1][ma] = (unsigned char)(sa1 != 0.f);
            sbuf[n][mb]     = (unsigned char)(sb0 != 0.f);
            sbuf[n + 1][mb] = (unsigned char)(sb1 != 0.f);
        }
    }
    __syncthreads();

    // Epilogue 2: coalesced plane-major stores.
    // tid = (g:3 | p:5); for each of 64 (m,t) pairs per group, 32 threads
    // write 32 consecutive pixels (consecutive hw) -> 128B transactions.
    {
        const int p = tid & 31;          // pixel within block (32 pixels)
        const int g = tid >> 5;          // 0..7
#pragma unroll 1
        for (int i = 0; i < 64; i++) {
            int mt_ = g * 64 + i;        // 0..511 -> (m, t)
            int m = mt_ >> 2;
            int t = mt_ & 3;
            int nloc = p * 4 + t;
            float s = (float)sbuf[nloc][m];
            out[colOff[nloc] + (mbase + m) * HW] = s;
        }
    }
}

// ===========================================================================
extern "C" void kernel_launch(void* const* d_in, const int* in_sizes, int n_in,
                              void* d_out, int out_size)
{
    const float* x          = (const float*)d_in[0];
    const float* q_w        = (const float*)d_in[1];
    const float* q_gamma    = (const float*)d_in[2];
    const float* q_beta     = (const float*)d_in[3];
    const float* q_mean     = (const float*)d_in[4];
    const float* q_var      = (const float*)d_in[5];
    const float* k_w        = (const float*)d_in[6];
    const float* k_gamma    = (const float*)d_in[7];
    const float* k_beta     = (const float*)d_in[8];
    const float* k_mean     = (const float*)d_in[9];
    const float* k_var      = (const float*)d_in[10];
    const float* proj_w     = (const float*)d_in[11];
    const float* proj_b     = (const float*)d_in[12];
    const float* proj_gamma = (const float*)d_in[13];
    const float* proj_beta  = (const float*)d_in[14];
    const float* proj_mean  = (const float*)d_in[15];
    const float* proj_var   = (const float*)d_in[16];

    __half *qw0, *qw1, *kw0, *kw1, *pw0, *pw1;
    cudaGetSymbolAddress((void**)&qw0, g_qw0);
    cudaGetSymbolAddress((void**)&qw1, g_qw1);
    cudaGetSymbolAddress((void**)&kw0, g_kw0);
    cudaGetSymbolAddress((void**)&kw1, g_kw1);
    cudaGetSymbolAddress((void**)&pw0, g_pw0);
    cudaGetSymbolAddress((void**)&pw1, g_pw1);
    float* qbn; float* kbn;
    cudaGetSymbolAddress((void**)&qbn, g_qbn);
    cudaGetSymbolAddress((void**)&kbn, g_kbn);

    dim3 ggrid(NTOT / 128, CH / 128);   // (196, 3)
    int wblocks = (CH * CH + 255) / 256;

    wsplit2_kernel<<<wblocks, 256>>>(q_w, qw0, qw1);
    wsplit2_kernel<<<wblocks, 256>>>(k_w, kw0, kw1);
    wsplit2_kernel<<<wblocks, 256>>>(proj_w, pw0, pw1);
    xsplit_kernel<<<dim3(T_STEPS * BATCH, CH / 32), dim3(32, 8)>>>(x);
    qk_mma_kernel<<<ggrid, 256>>>(qw0, qw1, q_gamma, q_beta, q_mean, q_var, qbn);
    qk_mma_kernel<<<ggrid, 256>>>(kw0, kw1, k_gamma, k_beta, k_mean, k_var, kbn);
    lif_attn_kernel<<<BATCH * HEADS, dim3(224, 4)>>>();
    proj_mma_kernel<<<ggrid, 256>>>(proj_gamma, proj_beta,
                                    proj_mean, proj_var, proj_b,
                                    (float*)d_out);
}

// round 15
// speedup vs baseline: 1.1932x; 1.0717x over previous
#include <cuda_runtime.h>
#include <cuda_fp16.h>
#include <cstdint>

// Problem constants
#define T_STEPS 4
#define BATCH   32
#define CH      384
#define HW      196
#define HEADS   8
#define DH      48
#define CHW     (CH*HW)          // 75264
#define BCHW    (BATCH*CHW)      // 2408448
#define TOTAL   (T_STEPS*BCHW)   // 9633792
#define NTOT    (T_STEPS*BATCH*HW) // 25088 (= 196 * 128 exactly)

// Scratch (static device globals -- allocation-guard safe)
__device__ unsigned char g_qsp[TOTAL];  // q spikes, [b][c][hw] x uchar4(t)
__device__ unsigned char g_ksp[TOTAL];  // k spikes, same layout
__device__ __half g_yhf[TOTAL];    // proj input, [n][c] row-major (n permuted), 0/1
__device__ __half g_pw0[CH*CH];    // proj_w 2-way fp16 split
__device__ __half g_pw1[CH*CH];
__device__ __half g_qw0[CH*CH];    // q_w split
__device__ __half g_qw1[CH*CH];
__device__ __half g_kw0[CH*CH];    // k_w split
__device__ __half g_kw1[CH*CH];
__device__ __half g_x0[TOTAL];     // X 2-way fp16 split, [n][k], n=(b*HW+hw)*4+t
__device__ __half g_x1[TOTAL];

// GEMM column permutation (qk AND proj): n = (b*HW + hw)*4 + t
__device__ __forceinline__ int proj_col_offset(int n) {
    int t   = n & 3;
    int bhw = n >> 2;
    int b   = bhw / HW;
    int hw  = bhw - b * HW;
    return t * BCHW + b * CHW + hw;     // element offset without channel term
}

__device__ __forceinline__ uint32_t smem_u32(const void* p) {
    uint32_t a;
    asm("{ .reg .u64 t; cvta.to.shared.u64 t, %1; cvt.u32.u64 %0, t; }"
        : "=r"(a) : "l"(p));
    return a;
}

#define MMA16816(CP, A0, A1, A2, A3, B0, B1)                                    \
    asm volatile(                                                               \
        "mma.sync.aligned.m16n8k16.row.col.f32.f16.f16.f32 "                    \
        "{%0,%1,%2,%3}, {%4,%5,%6,%7}, {%8,%9}, {%0,%1,%2,%3};"                 \
        : "+f"((CP)[0]), "+f"((CP)[1]), "+f"((CP)[2]), "+f"((CP)[3])            \
        : "r"(A0), "r"(A1), "r"(A2), "r"(A3), "r"(B0), "r"(B1))

#define LDMX4(R0, R1, R2, R3, AD)                                               \
    asm volatile("ldmatrix.sync.aligned.m8n8.x4.shared.b16 {%0,%1,%2,%3}, [%4];"\
        : "=r"(R0), "=r"(R1), "=r"(R2), "=r"(R3) : "r"(AD))

// Fused LIF over a lane pair: even lane holds (t0,t1), odd lane (t2,t3) of
// one pixel; shfl_xor(1) carries the membrane. v_th = 1.0. Proven R12/R13.
__device__ __forceinline__ void lif_pair(int lane, float z0, float z1,
                                         float& s0, float& s1)
{
    float h0 = z0 * 0.5f;               // vstart = 0 (even lane)
    bool  a0 = h0 >= 1.0f;
    float v  = a0 ? 0.f : h0;
    float h1 = v + (z1 - v) * 0.5f;
    bool  a1 = h1 >= 1.0f;
    float v1 = a1 ? 0.f : h1;
    float vin = __shfl_xor_sync(0xffffffffu, v1, 1);
    if (lane & 1) {                     // odd lane: redo with carried membrane
        h0 = vin + (z0 - vin) * 0.5f;
        a0 = h0 >= 1.0f;
        v  = a0 ? 0.f : h0;
        h1 = v + (z1 - v) * 0.5f;
        a1 = h1 >= 1.0f;
    }
    s0 = a0 ? 1.f : 0.f;
    s1 = a1 ? 1.f : 0.f;
}

// ===========================================================================
// all-weights 2-way fp16 split in one launch (blockIdx.y selects tensor)
// ===========================================================================
__global__ void wsplit_all_kernel(const float* __restrict__ qw,
                                  const float* __restrict__ kw,
                                  const float* __restrict__ pw)
{
    int i = blockIdx.x * blockDim.x + threadIdx.x;
    if (i >= CH * CH) return;
    const float* src = (blockIdx.y == 0) ? qw : (blockIdx.y == 1) ? kw : pw;
    __half* d0 = (blockIdx.y == 0) ? g_qw0 : (blockIdx.y == 1) ? g_kw0 : g_pw0;
    __half* d1 = (blockIdx.y == 0) ? g_qw1 : (blockIdx.y == 1) ? g_kw1 : g_pw1;
    float v = src[i];
    __half h0 = __float2half_rn(v);
    __half h1 = __float2half_rn(v - __half2float(h0));
    d0[i] = h0; d1[i] = h1;
}

// ===========================================================================
// X transpose + 2-way fp16 split:  X[t][b][c][hw] -> planes[n][c],
// n = (b*HW+hw)*4 + t   (permuted GEMM column order)
// ===========================================================================
__global__ void __launch_bounds__(256) xsplit_kernel(const float* __restrict__ X)
{
    __shared__ float tile[32][33];
    const int tb = blockIdx.x;           // t*BATCH + b
    const int t  = tb >> 5;
    const int b  = tb & 31;
    const int c0 = blockIdx.y * 32;
    const int tx = threadIdx.x, ty = threadIdx.y;

#pragma unroll 1
    for (int hw0 = 0; hw0 < HW; hw0 += 32) {
        __syncthreads();
#pragma unroll
        for (int i = 0; i < 4; i++) {
            int c  = c0 + ty + i * 8;
            int hw = hw0 + tx;
            tile[ty + i * 8][tx] = (hw < HW) ? X[tb * CHW + c * HW + hw] : 0.f;
        }
        __syncthreads();
#pragma unroll
        for (int i = 0; i < 4; i++) {
            int hw = hw0 + ty + i * 8;
            if (hw < HW) {
                float v = tile[tx][ty + i * 8];
                __half h0 = __float2half_rn(v);
                __half h1 = __float2half_rn(v - __half2float(h0));
                size_t o = ((size_t)(b * HW + hw) * 4 + t) * CH + c0 + tx;
                g_x0[o] = h0; g_x1[o] = h1;
            }
        }
    }
}

// ===========================================================================
// Q/K GEMM via 3-term fp16-split mma.sync + FUSED per-channel LIF.
//   D = w0@x0 + w1@x0 + w0@x1 ; BN ; LIF over T (lane pair) -> spike BYTES.
// Output layout: [b][c][hw] x uchar4(t) -- coalesced uchar4 stores.
// sbuf aliases sA (dead after mainloop) to stay under 48KB static smem.
// ===========================================================================
#define KC      32
#define PITCH   40

__global__ void __launch_bounds__(256, 2) qk_mma_kernel(
    const __half* __restrict__ w0,
    const __half* __restrict__ w1,
    const float* __restrict__ gamma, const float* __restrict__ beta,
    const float* __restrict__ mean,  const float* __restrict__ var,
    unsigned char* __restrict__ out)
{
    __shared__ __half sA[2][128][PITCH];
    __shared__ __half sB[2][128][PITCH];

    const int tid  = threadIdx.x;
    const int wid  = tid >> 5;
    const int lane = tid & 31;
    const int mbase = blockIdx.y * 128;
    const int nbase = blockIdx.x * 128;

    const int wm = (wid & 3) * 32;
    const int wn = (wid >> 2) * 64;

    const int a_r  = (lane & 7) + ((lane >> 3) & 1) * 8;
    const int a_kc = (lane >> 4) * 8;
    const int b_r  = (lane & 7) + (lane >> 4) * 8;
    const int b_kc = ((lane >> 3) & 1) * 8;

    const __half* ga[2] = { w0 + (size_t)mbase * CH, w1 + (size_t)mbase * CH };
    const __half* gb[2] = { g_x0 + (size_t)nbase * CH, g_x1 + (size_t)nbase * CH };

    float acc[2][8][4];
#pragma unroll
    for (int mt = 0; mt < 2; mt++)
#pragma unroll
        for (int nt = 0; nt < 8; nt++)
#pragma unroll
            for (int r = 0; r < 4; r++) acc[mt][nt][r] = 0.f;

    const int l_row = tid >> 2;
    const int l_q   = (tid & 3) * 8;

#pragma unroll 1
    for (int kc = 0; kc < CH / KC; kc++) {
        const int kbase = kc * KC;
        __syncthreads();
#pragma unroll
        for (int r2 = 0; r2 < 2; r2++) {
            const int row = l_row + r2 * 64;
#pragma unroll
            for (int p = 0; p < 2; p++) {
                *reinterpret_cast<uint4*>(&sA[p][row][l_q]) =
                    *reinterpret_cast<const uint4*>(ga[p] + (size_t)row * CH + kbase + l_q);
                *reinterpret_cast<uint4*>(&sB[p][row][l_q]) =
                    *reinterpret_cast<const uint4*>(gb[p] + (size_t)row * CH + kbase + l_q);
            }
        }
        __syncthreads();

#pragma unroll
        for (int kk = 0; kk < 2; kk++) {
            const int k0 = kk * 16;
            uint32_t a[2][2][4];
#pragma unroll
            for (int p = 0; p < 2; p++)
#pragma unroll
                for (int mt = 0; mt < 2; mt++) {
                    uint32_t ad = smem_u32(&sA[p][wm + mt * 16 + a_r][k0 + a_kc]);
                    LDMX4(a[p][mt][0], a[p][mt][1], a[p][mt][2], a[p][mt][3], ad);
                }
#pragma unroll
            for (int nt2 = 0; nt2 < 4; nt2++) {
                uint32_t b[2][4];
#pragma unroll
                for (int p = 0; p < 2; p++) {
                    uint32_t bd = smem_u32(&sB[p][wn + nt2 * 16 + b_r][k0 + b_kc]);
                    LDMX4(b[p][0], b[p][1], b[p][2], b[p][3], bd);
                }
#define QK_PAIR(I, J)                                                           \
                _Pragma("unroll")                                               \
                for (int mt = 0; mt < 2; mt++) {                                \
                    MMA16816(acc[mt][nt2 * 2],                                  \
                             a[I][mt][0], a[I][mt][1], a[I][mt][2], a[I][mt][3],\
                             b[J][0], b[J][1]);                                 \
                    MMA16816(acc[mt][nt2 * 2 + 1],                              \
                             a[I][mt][0], a[I][mt][1], a[I][mt][2], a[I][mt][3],\
                             b[J][2], b[J][3]);                                 \
                }
                QK_PAIR(0, 0)
                QK_PAIR(1, 0)
                QK_PAIR(0, 1)
#undef QK_PAIR
            }
        }
    }

    // Epilogue 1: BN -> fused LIF -> spike bytes into sbuf (aliases dead sA)
    __syncthreads();
    unsigned char (*sbuf)[132] = reinterpret_cast<unsigned char(*)[132]>(&sA[0][0][0]);
#pragma unroll
    for (int mt = 0; mt < 2; mt++) {
        int ma = wm + mt * 16 + (lane >> 2);
        int mb = ma + 8;
        int oa = mbase + ma, ob = mbase + mb;
        float inva = gamma[oa] / sqrtf(var[oa] + 1e-5f);
        float sha  = beta[oa] - mean[oa] * inva;
        float invb = gamma[ob] / sqrtf(var[ob] + 1e-5f);
        float shb  = beta[ob] - mean[ob] * invb;
#pragma unroll
        for (int nt = 0; nt < 8; nt++) {
            int n = wn + nt * 8 + (lane & 3) * 2;
            const float* c = acc[mt][nt];
            float za0 = c[0] * inva + sha;
            float za1 = c[1] * inva + sha;
            float zb0 = c[2] * invb + shb;
            float zb1 = c[3] * invb + shb;
            float sa0, sa1, sb0, sb1;
            lif_pair(lane, za0, za1, sa0, sa1);
            lif_pair(lane, zb0, zb1, sb0, sb1);
            sbuf[n][ma]     = (unsigned char)(sa0 != 0.f);
            sbuf[n + 1][ma] = (unsigned char)(sa1 != 0.f);
            sbuf[n][mb]     = (unsigned char)(sb0 != 0.f);
            sbuf[n + 1][mb] = (unsigned char)(sb1 != 0.f);
        }
    }
    __syncthreads();

    // Epilogue 2: coalesced uchar4 stores; per (m), 32 threads store 32
    // consecutive pixels' t-quads -> 128B transactions.
    {
        const int p  = tid & 31;         // pixel within block (32 pixels)
        const int g  = tid >> 5;         // 0..7
        int pix = (nbase >> 2) + p;
        int b   = pix / HW;
        int hw  = pix - b * HW;
        int pb  = b * CHW + hw;
#pragma unroll 1
        for (int i = 0; i < 16; i++) {
            int m = g * 16 + i;
            uchar4 v;
            v.x = sbuf[p * 4 + 0][m];
            v.y = sbuf[p * 4 + 1][m];
            v.z = sbuf[p * 4 + 2][m];
            v.w = sbuf[p * 4 + 3][m];
            *reinterpret_cast<uchar4*>(out + (size_t)(pb + (mbase + m) * HW) * 4) = v;
        }
    }
}

// ===========================================================================
// Attention gate: read q/k spike bytes, per-head sum, attn LIF (vth=0.5),
// gate k -> y as fp16 [n][c] (n permuted).
// ===========================================================================
__device__ __forceinline__ uint32_t pk2h(uint32_t m) {
    return ((m & 1u) ? 0x3C00u : 0u) | ((m & 2u) ? 0x3C000000u : 0u);
}

__global__ void __launch_bounds__(896) lif_attn_kernel()
{
    __shared__ int      s_qs[4][224][4];
    __shared__ uint32_t s_kb[4][224][4];
    __shared__ uint32_t s_m[224][4][2];

    const int bh   = blockIdx.x;
    const int b    = bh >> 3;
    const int head = bh & 7;
    const int hw   = threadIdx.x;
    const int dg   = threadIdx.y;
    const bool act = hw < HW;

    const int cb = head * DH + dg * 12;

    int      qs[4] = {0, 0, 0, 0};
    uint32_t kb[4] = {0u, 0u, 0u, 0u};

    if (act) {
        const uchar4* q4 = reinterpret_cast<const uchar4*>(g_qsp);
        const uchar4* k4 = reinterpret_cast<const uchar4*>(g_ksp);
#pragma unroll
        for (int d = 0; d < 12; d++) {
            int ci = b * CHW + (cb + d) * HW + hw;
            uchar4 qv = q4[ci];
            uchar4 kv = k4[ci];
            qs[0] += qv.x; qs[1] += qv.y; qs[2] += qv.z; qs[3] += qv.w;
            kb[0] |= (uint32_t)(kv.x & 1) << d;
            kb[1] |= (uint32_t)(kv.y & 1) << d;
            kb[2] |= (uint32_t)(kv.z & 1) << d;
            kb[3] |= (uint32_t)(kv.w & 1) << d;
        }
    }
#pragma unroll
    for (int t = 0; t < 4; t++) {
        s_qs[dg][hw][t] = qs[t];
        s_kb[dg][hw][t] = kb[t];
    }
    __syncthreads();

    if (dg == 0 && act) {
        float va = 0.f;
#pragma unroll
        for (int t = 0; t < 4; t++) {
            float q = (float)(qs[t] + s_qs[1][hw][t] + s_qs[2][hw][t] + s_qs[3][hw][t]);
            uint32_t m0 = kb[t] | (s_kb[1][hw][t] << 12);
            uint32_t m1 = s_kb[2][hw][t] | (s_kb[3][hw][t] << 12);
            float h = va + (q - va) * 0.5f;
            bool s  = (h - 0.5f) >= 0.0f;
            va = s ? 0.f : h;
            s_m[hw][t][0] = s ? m0 : 0u;
            s_m[hw][t][1] = s ? m1 : 0u;
        }
    }
    __syncthreads();

    const int tidl = dg * 224 + hw;
#pragma unroll 1
    for (int l = tidl; l < HW * 4 * 6; l += 896) {
        int g  = l % 6;
        int r  = l / 6;
        int whw = r % HW;
        int t   = r / HW;
        uint32_t mask = s_m[whw][t][g >= 3 ? 1 : 0];
        uint32_t bits = mask >> ((g >= 3 ? g - 3 : g) * 8);
        uint4 v;
        v.x = pk2h(bits);
        v.y = pk2h(bits >> 2);
        v.z = pk2h(bits >> 4);
        v.w = pk2h(bits >> 6);
        size_t n = (size_t)(b * HW + whw) * 4 + t;        // permuted column order
        uint4* dst = reinterpret_cast<uint4*>(g_yhf + n * CH + head * DH);
        dst[g] = v;
    }
}

// ===========================================================================
// proj GEMM (2-term fp16 split) + FUSED final LIF (permuted cols) -- R13 form
// ===========================================================================
#define SBP 132

__global__ void __launch_bounds__(256, 2) proj_mma_kernel(
    const float* __restrict__ gamma, const float* __restrict__ beta,
    const float* __restrict__ mean,  const float* __restrict__ var,
    const float* __restrict__ bias,  float* __restrict__ out)
{
    __shared__ __half sA[2][128][PITCH];
    __shared__ __half sB[128][PITCH];
    __shared__ unsigned char sbuf[128][SBP];
    __shared__ int colOff[128];

    const int tid  = threadIdx.x;
    const int wid  = tid >> 5;
    const int lane = tid & 31;
    const int mbase = blockIdx.y * 128;
    const int nbase = blockIdx.x * 128;

    if (tid < 128) colOff[tid] = proj_col_offset(nbase + tid);

    const int wm = (wid & 3) * 32;
    const int wn = (wid >> 2) * 64;

    const int a_r  = (lane & 7) + ((lane >> 3) & 1) * 8;
    const int a_kc = (lane >> 4) * 8;
    const int b_r  = (lane & 7) + (lane >> 4) * 8;
    const int b_kc = ((lane >> 3) & 1) * 8;

    const __half* ga[2] = { g_pw0 + (size_t)mbase * CH, g_pw1 + (size_t)mbase * CH };
    const __half* gy = g_yhf + (size_t)nbase * CH;

    float acc[2][8][4];
#pragma unroll
    for (int mt = 0; mt < 2; mt++)
#pragma unroll
        for (int nt = 0; nt < 8; nt++)
#pragma unroll
            for (int r = 0; r < 4; r++) acc[mt][nt][r] = 0.f;

    const int l_row = tid >> 2;
    const int l_q   = (tid & 3) * 8;

#pragma unroll 1
    for (int kc = 0; kc < CH / KC; kc++) {
        const int kbase = kc * KC;
        __syncthreads();
#pragma unroll
        for (int r2 = 0; r2 < 2; r2++) {
            const int row = l_row + r2 * 64;
#pragma unroll
            for (int p = 0; p < 2; p++)
                *reinterpret_cast<uint4*>(&sA[p][row][l_q]) =
                    *reinterpret_cast<const uint4*>(ga[p] + (size_t)row * CH + kbase + l_q);
            *reinterpret_cast<uint4*>(&sB[row][l_q]) =
                *reinterpret_cast<const uint4*>(gy + (size_t)row * CH + kbase + l_q);
        }
        __syncthreads();

#pragma unroll
        for (int kk = 0; kk < 2; kk++) {
            const int k0 = kk * 16;
            uint32_t a[2][2][4];
#pragma unroll
            for (int p = 0; p < 2; p++)
#pragma unroll
                for (int mt = 0; mt < 2; mt++) {
                    uint32_t ad = smem_u32(&sA[p][wm + mt * 16 + a_r][k0 + a_kc]);
                    LDMX4(a[p][mt][0], a[p][mt][1], a[p][mt][2], a[p][mt][3], ad);
                }
#pragma unroll
            for (int nt2 = 0; nt2 < 4; nt2++) {
                uint32_t b0, b1, b2, b3;
                uint32_t bd = smem_u32(&sB[wn + nt2 * 16 + b_r][k0 + b_kc]);
                LDMX4(b0, b1, b2, b3, bd);
#pragma unroll
                for (int p = 0; p < 2; p++)
#pragma unroll
                    for (int mt = 0; mt < 2; mt++) {
                        MMA16816(acc[mt][nt2 * 2],
                                 a[p][mt][0], a[p][mt][1], a[p][mt][2], a[p][mt][3],
                                 b0, b1);
                        MMA16816(acc[mt][nt2 * 2 + 1],
                                 a[p][mt][0], a[p][mt][1], a[p][mt][2], a[p][mt][3],
                                 b2, b3);
                    }
            }
        }
    }

    __syncthreads();
#pragma unroll
    for (int mt = 0; mt < 2; mt++) {
        int ma = wm + mt * 16 + (lane >> 2);
        int mb = ma + 8;
        int oa = mbase + ma, ob = mbase + mb;
        float inva = gamma[oa] / sqrtf(var[oa] + 1e-5f);
        float sha  = beta[oa] - mean[oa] * inva;
        float bva  = bias[oa];
        float invb = gamma[ob] / sqrtf(var[ob] + 1e-5f);
        float shb  = beta[ob] - mean[ob] * invb;
        float bvb  = bias[ob];
#pragma unroll
        for (int nt = 0; nt < 8; nt++) {
            int n = wn + nt * 8 + (lane & 3) * 2;
            const float* c = acc[mt][nt];
            float za0 = (c[0] + bva) * inva + sha;
            float za1 = (c[1] + bva) * inva + sha;
            float zb0 = (c[2] + bvb) * invb + shb;
            float zb1 = (c[3] + bvb) * invb + shb;
            float sa0, sa1, sb0, sb1;
            lif_pair(lane, za0, za1, sa0, sa1);
            lif_pair(lane, zb0, zb1, sb0, sb1);
            sbuf[n][ma]     = (unsigned char)(sa0 != 0.f);
            sbuf[n + 1][ma] = (unsigned char)(sa1 != 0.f);
            sbuf[n][mb]     = (unsigned char)(sb0 != 0.f);
            sbuf[n + 1][mb] = (unsigned char)(sb1 != 0.f);
        }
    }
    __syncthreads();

    {
        const int p = tid & 31;
        const int g = tid >> 5;
#pragma unroll 1
        for (int i = 0; i < 64; i++) {
            int mt_ = g * 64 + i;
            int m = mt_ >> 2;
            int t = mt_ & 3;
            int nloc = p * 4 + t;
            float s = (float)sbuf[nloc][m];
            out[colOff[nloc] + (mbase + m) * HW] = s;
        }
    }
}

// ===========================================================================
extern "C" void kernel_launch(void* const* d_in, const int* in_sizes, int n_in,
                              void* d_out, int out_size)
{
    const float* x          = (const float*)d_in[0];
    const float* q_w        = (const float*)d_in[1];
    const float* q_gamma    = (const float*)d_in[2];
    const float* q_beta     = (const float*)d_in[3];
    const float* q_mean     = (const float*)d_in[4];
    const float* q_var      = (const float*)d_in[5];
    const float* k_w        = (const float*)d_in[6];
    const float* k_gamma    = (const float*)d_in[7];
    const float* k_beta     = (const float*)d_in[8];
    const float* k_mean     = (const float*)d_in[9];
    const float* k_var      = (const float*)d_in[10];
    const float* proj_w     = (const float*)d_in[11];
    const float* proj_b     = (const float*)d_in[12];
    const float* proj_gamma = (const float*)d_in[13];
    const float* proj_beta  = (const float*)d_in[14];
    const float* proj_mean  = (const float*)d_in[15];
    const float* proj_var   = (const float*)d_in[16];

    __half *qw0, *qw1, *kw0, *kw1;
    cudaGetSymbolAddress((void**)&qw0, g_qw0);
    cudaGetSymbolAddress((void**)&qw1, g_qw1);
    cudaGetSymbolAddress((void**)&kw0, g_kw0);
    cudaGetSymbolAddress((void**)&kw1, g_kw1);
    unsigned char *qsp, *ksp;
    cudaGetSymbolAddress((void**)&qsp, g_qsp);
    cudaGetSymbolAddress((void**)&ksp, g_ksp);

    dim3 ggrid(NTOT / 128, CH / 128);   // (196, 3)
    int wblocks = (CH * CH + 255) / 256;

    wsplit_all_kernel<<<dim3(wblocks, 3), 256>>>(q_w, k_w, proj_w);
    xsplit_kernel<<<dim3(T_STEPS * BATCH, CH / 32), dim3(32, 8)>>>(x);
    qk_mma_kernel<<<ggrid, 256>>>(qw0, qw1, q_gamma, q_beta, q_mean, q_var, qsp);
    qk_mma_kernel<<<ggrid, 256>>>(kw0, kw1, k_gamma, k_beta, k_mean, k_var, ksp);
    lif_attn_kernel<<<BATCH * HEADS, dim3(224, 4)>>>();
    proj_mma_kernel<<<ggrid, 256>>>(proj_gamma, proj_beta,
                                    proj_mean, proj_var, proj_b,
                                    (float*)d_out);
}

// round 16
// speedup vs baseline: 1.2258x; 1.0273x over previous
#include <cuda_runtime.h>
#include <cuda_fp16.h>
#include <cstdint>

// Problem constants
#define T_STEPS 4
#define BATCH   32
#define CH      384
#define HW      196
#define HEADS   8
#define DH      48
#define CHW     (CH*HW)          // 75264
#define BCHW    (BATCH*CHW)      // 2408448
#define TOTAL   (T_STEPS*BCHW)   // 9633792
#define NTOT    (T_STEPS*BATCH*HW) // 25088 (= 196 * 128 exactly)

// Scratch (static device globals -- allocation-guard safe)
__device__ unsigned char g_qsp[TOTAL];  // q spikes, [b][c][hw] x uchar4(t)
__device__ unsigned char g_ksp[TOTAL];  // k spikes, same layout
__device__ __half g_yhf[TOTAL];    // proj input, [n][c] row-major (n permuted), 0/1
__device__ __half g_pw0[CH*CH];    // proj_w 2-way fp16 split
__device__ __half g_pw1[CH*CH];
__device__ __half g_qw0[CH*CH];    // q_w split
__device__ __half g_qw1[CH*CH];
__device__ __half g_kw0[CH*CH];    // k_w split
__device__ __half g_kw1[CH*CH];
__device__ __half g_x0[TOTAL];     // X 2-way fp16 split, [n][k], n=(b*HW+hw)*4+t
__device__ __half g_x1[TOTAL];

// GEMM column permutation: n = (b*HW + hw)*4 + t
__device__ __forceinline__ int proj_col_offset(int n) {
    int t   = n & 3;
    int bhw = n >> 2;
    int b   = bhw / HW;
    int hw  = bhw - b * HW;
    return t * BCHW + b * CHW + hw;     // element offset without channel term
}

__device__ __forceinline__ uint32_t smem_u32(const void* p) {
    uint32_t a;
    asm("{ .reg .u64 t; cvta.to.shared.u64 t, %1; cvt.u32.u64 %0, t; }"
        : "=r"(a) : "l"(p));
    return a;
}

#define MMA16816(CP, A0, A1, A2, A3, B0, B1)                                    \
    asm volatile(                                                               \
        "mma.sync.aligned.m16n8k16.row.col.f32.f16.f16.f32 "                    \
        "{%0,%1,%2,%3}, {%4,%5,%6,%7}, {%8,%9}, {%0,%1,%2,%3};"                 \
        : "+f"((CP)[0]), "+f"((CP)[1]), "+f"((CP)[2]), "+f"((CP)[3])            \
        : "r"(A0), "r"(A1), "r"(A2), "r"(A3), "r"(B0), "r"(B1))

#define LDMX4(R0, R1, R2, R3, AD)                                               \
    asm volatile("ldmatrix.sync.aligned.m8n8.x4.shared.b16 {%0,%1,%2,%3}, [%4];"\
        : "=r"(R0), "=r"(R1), "=r"(R2), "=r"(R3) : "r"(AD))

#define CPASYNC16(DST, SRC)                                                     \
    asm volatile("cp.async.cg.shared.global [%0], [%1], 16;"                    \
        :: "r"(DST), "l"(SRC) : "memory")
#define CP_COMMIT()   asm volatile("cp.async.commit_group;" ::: "memory")
#define CP_WAIT_ALL() asm volatile("cp.async.wait_group 0;" ::: "memory")

// Fused LIF over a lane pair (proven R12-R14): even lane (t0,t1), odd (t2,t3).
__device__ __forceinline__ void lif_pair(int lane, float z0, float z1,
                                         float& s0, float& s1)
{
    float h0 = z0 * 0.5f;
    bool  a0 = h0 >= 1.0f;
    float v  = a0 ? 0.f : h0;
    float h1 = v + (z1 - v) * 0.5f;
    bool  a1 = h1 >= 1.0f;
    float v1 = a1 ? 0.f : h1;
    float vin = __shfl_xor_sync(0xffffffffu, v1, 1);
    if (lane & 1) {
        h0 = vin + (z0 - vin) * 0.5f;
        a0 = h0 >= 1.0f;
        v  = a0 ? 0.f : h0;
        h1 = v + (z1 - v) * 0.5f;
        a1 = h1 >= 1.0f;
    }
    s0 = a0 ? 1.f : 0.f;
    s1 = a1 ? 1.f : 0.f;
}

// ===========================================================================
// all-weights 2-way fp16 split in one launch
// ===========================================================================
__global__ void wsplit_all_kernel(const float* __restrict__ qw,
                                  const float* __restrict__ kw,
                                  const float* __restrict__ pw)
{
    int i = blockIdx.x * blockDim.x + threadIdx.x;
    if (i >= CH * CH) return;
    const float* src = (blockIdx.y == 0) ? qw : (blockIdx.y == 1) ? kw : pw;
    __half* d0 = (blockIdx.y == 0) ? g_qw0 : (blockIdx.y == 1) ? g_kw0 : g_pw0;
    __half* d1 = (blockIdx.y == 0) ? g_qw1 : (blockIdx.y == 1) ? g_kw1 : g_pw1;
    float v = src[i];
    __half h0 = __float2half_rn(v);
    __half h1 = __float2half_rn(v - __half2float(h0));
    d0[i] = h0; d1[i] = h1;
}

// ===========================================================================
// X transpose + 2-way fp16 split -> planes[n][c], n = (b*HW+hw)*4 + t
// ===========================================================================
__global__ void __launch_bounds__(256) xsplit_kernel(const float* __restrict__ X)
{
    __shared__ float tile[32][33];
    const int tb = blockIdx.x;
    const int t  = tb >> 5;
    const int b  = tb & 31;
    const int c0 = blockIdx.y * 32;
    const int tx = threadIdx.x, ty = threadIdx.y;

#pragma unroll 1
    for (int hw0 = 0; hw0 < HW; hw0 += 32) {
        __syncthreads();
#pragma unroll
        for (int i = 0; i < 4; i++) {
            int c  = c0 + ty + i * 8;
            int hw = hw0 + tx;
            tile[ty + i * 8][tx] = (hw < HW) ? X[tb * CHW + c * HW + hw] : 0.f;
        }
        __syncthreads();
#pragma unroll
        for (int i = 0; i < 4; i++) {
            int hw = hw0 + ty + i * 8;
            if (hw < HW) {
                float v = tile[tx][ty + i * 8];
                __half h0 = __float2half_rn(v);
                __half h1 = __float2half_rn(v - __half2float(h0));
                size_t o = ((size_t)(b * HW + hw) * 4 + t) * CH + c0 + tx;
                g_x0[o] = h0; g_x1[o] = h1;
            }
        }
    }
}

// ===========================================================================
// Q/K GEMM: 3-term fp16-split mma + fused LIF, now with 2-stage cp.async
// pipeline (KC=32, PITCH=40 geometry unchanged). One __syncthreads/chunk.
// Dynamic smem: 2 stages x 4 planes x [128][40] fp16 = 80 KB; sbuf aliases.
// ===========================================================================
#define KC      32
#define PITCH   40
#define QK_PLANES   4
#define QK_STAGE_B  (QK_PLANES * 128 * PITCH * 2)       // 40960
#define QK_DSMEM    (2 * QK_STAGE_B)                    // 81920

__global__ void __launch_bounds__(256, 2) qk_mma_kernel(
    const __half* __restrict__ w0,
    const __half* __restrict__ w1,
    const float* __restrict__ gamma, const float* __restrict__ beta,
    const float* __restrict__ mean,  const float* __restrict__ var,
    unsigned char* __restrict__ out)
{
    extern __shared__ char dsm[];
    __half* sP = reinterpret_cast<__half*>(dsm);
    // plane index: 0,1 = A(w0,w1); 2,3 = B(x0,x1)
#define QSP(S, P, R, C) sP[(((S) * QK_PLANES + (P)) * 128 + (R)) * PITCH + (C)]

    const int tid  = threadIdx.x;
    const int wid  = tid >> 5;
    const int lane = tid & 31;
    const int mbase = blockIdx.y * 128;
    const int nbase = blockIdx.x * 128;

    const int wm = (wid & 3) * 32;
    const int wn = (wid >> 2) * 64;

    const int a_r  = (lane & 7) + ((lane >> 3) & 1) * 8;
    const int a_kc = (lane >> 4) * 8;
    const int b_r  = (lane & 7) + (lane >> 4) * 8;
    const int b_kc = ((lane >> 3) & 1) * 8;

    const __half* gsrc[QK_PLANES] = {
        w0 + (size_t)mbase * CH, w1 + (size_t)mbase * CH,
        g_x0 + (size_t)nbase * CH, g_x1 + (size_t)nbase * CH };

    const int l_row = tid >> 2;          // 0..63 (+64 second pass)
    const int l_q   = (tid & 3) * 8;

#define QK_LOAD(KC_)                                                            \
    do {                                                                        \
        int s_ = (KC_) & 1;                                                     \
        int ko_ = (KC_) * KC + l_q;                                             \
        _Pragma("unroll")                                                       \
        for (int r2 = 0; r2 < 2; r2++) {                                        \
            int row_ = l_row + r2 * 64;                                         \
            _Pragma("unroll")                                                   \
            for (int p = 0; p < QK_PLANES; p++)                                 \
                CPASYNC16(smem_u32(&QSP(s_, p, row_, l_q)),                     \
                          gsrc[p] + (size_t)row_ * CH + ko_);                   \
        }                                                                       \
        CP_COMMIT();                                                            \
    } while (0)

    float acc[2][8][4];
#pragma unroll
    for (int mt = 0; mt < 2; mt++)
#pragma unroll
        for (int nt = 0; nt < 8; nt++)
#pragma unroll
            for (int r = 0; r < 4; r++) acc[mt][nt][r] = 0.f;

    QK_LOAD(0);

#pragma unroll 1
    for (int kc = 0; kc < CH / KC; kc++) {
        CP_WAIT_ALL();
        __syncthreads();
        if (kc + 1 < CH / KC) QK_LOAD(kc + 1);

        const int s = kc & 1;
#pragma unroll
        for (int kk = 0; kk < 2; kk++) {
            const int k0 = kk * 16;
            uint32_t a[2][2][4];
#pragma unroll
            for (int p = 0; p < 2; p++)
#pragma unroll
                for (int mt = 0; mt < 2; mt++) {
                    uint32_t ad = smem_u32(&QSP(s, p, wm + mt * 16 + a_r, k0 + a_kc));
                    LDMX4(a[p][mt][0], a[p][mt][1], a[p][mt][2], a[p][mt][3], ad);
                }
#pragma unroll
            for (int nt2 = 0; nt2 < 4; nt2++) {
                uint32_t b[2][4];
#pragma unroll
                for (int p = 0; p < 2; p++) {
                    uint32_t bd = smem_u32(&QSP(s, p + 2, wn + nt2 * 16 + b_r, k0 + b_kc));
                    LDMX4(b[p][0], b[p][1], b[p][2], b[p][3], bd);
                }
#define QK_PAIR(I, J)                                                           \
                _Pragma("unroll")                                               \
                for (int mt = 0; mt < 2; mt++) {                                \
                    MMA16816(acc[mt][nt2 * 2],                                  \
                             a[I][mt][0], a[I][mt][1], a[I][mt][2], a[I][mt][3],\
                             b[J][0], b[J][1]);                                 \
                    MMA16816(acc[mt][nt2 * 2 + 1],                              \
                             a[I][mt][0], a[I][mt][1], a[I][mt][2], a[I][mt][3],\
                             b[J][2], b[J][3]);                                 \
                }
                QK_PAIR(0, 0)
                QK_PAIR(1, 0)
                QK_PAIR(0, 1)
#undef QK_PAIR
            }
        }
    }
#undef QK_LOAD

    // Epilogue 1: BN -> fused LIF -> spike bytes into sbuf (aliases stages)
    __syncthreads();
    unsigned char (*sbuf)[132] = reinterpret_cast<unsigned char(*)[132]>(dsm);
#pragma unroll
    for (int mt = 0; mt < 2; mt++) {
        int ma = wm + mt * 16 + (lane >> 2);
        int mb = ma + 8;
        int oa = mbase + ma, ob = mbase + mb;
        float inva = gamma[oa] / sqrtf(var[oa] + 1e-5f);
        float sha  = beta[oa] - mean[oa] * inva;
        float invb = gamma[ob] / sqrtf(var[ob] + 1e-5f);
        float shb  = beta[ob] - mean[ob] * invb;
#pragma unroll
        for (int nt = 0; nt < 8; nt++) {
            int n = wn + nt * 8 + (lane & 3) * 2;
            const float* c = acc[mt][nt];
            float za0 = c[0] * inva + sha;
            float za1 = c[1] * inva + sha;
            float zb0 = c[2] * invb + shb;
            float zb1 = c[3] * invb + shb;
            float sa0, sa1, sb0, sb1;
            lif_pair(lane, za0, za1, sa0, sa1);
            lif_pair(lane, zb0, zb1, sb0, sb1);
            sbuf[n][ma]     = (unsigned char)(sa0 != 0.f);
            sbuf[n + 1][ma] = (unsigned char)(sa1 != 0.f);
            sbuf[n][mb]     = (unsigned char)(sb0 != 0.f);
            sbuf[n + 1][mb] = (unsigned char)(sb1 != 0.f);
        }
    }
    __syncthreads();

    // Epilogue 2: coalesced uchar4 stores
    {
        const int p  = tid & 31;
        const int g  = tid >> 5;
        int pix = (nbase >> 2) + p;
        int b   = pix / HW;
        int hw  = pix - b * HW;
        int pb  = b * CHW + hw;
#pragma unroll 1
        for (int i = 0; i < 16; i++) {
            int m = g * 16 + i;
            uchar4 v;
            v.x = sbuf[p * 4 + 0][m];
            v.y = sbuf[p * 4 + 1][m];
            v.z = sbuf[p * 4 + 2][m];
            v.w = sbuf[p * 4 + 3][m];
            *reinterpret_cast<uchar4*>(out + (size_t)(pb + (mbase + m) * HW) * 4) = v;
        }
    }
#undef QSP
}

// ===========================================================================
// Attention gate (R14 form): spike bytes in, gated y (fp16, permuted) out
// ===========================================================================
__device__ __forceinline__ uint32_t pk2h(uint32_t m) {
    return ((m & 1u) ? 0x3C00u : 0u) | ((m & 2u) ? 0x3C000000u : 0u);
}

__global__ void __launch_bounds__(896) lif_attn_kernel()
{
    __shared__ int      s_qs[4][224][4];
    __shared__ uint32_t s_kb[4][224][4];
    __shared__ uint32_t s_m[224][4][2];

    const int bh   = blockIdx.x;
    const int b    = bh >> 3;
    const int head = bh & 7;
    const int hw   = threadIdx.x;
    const int dg   = threadIdx.y;
    const bool act = hw < HW;

    const int cb = head * DH + dg * 12;

    int      qs[4] = {0, 0, 0, 0};
    uint32_t kb[4] = {0u, 0u, 0u, 0u};

    if (act) {
        const uchar4* q4 = reinterpret_cast<const uchar4*>(g_qsp);
        const uchar4* k4 = reinterpret_cast<const uchar4*>(g_ksp);
#pragma unroll
        for (int d = 0; d < 12; d++) {
            int ci = b * CHW + (cb + d) * HW + hw;
            uchar4 qv = q4[ci];
            uchar4 kv = k4[ci];
            qs[0] += qv.x; qs[1] += qv.y; qs[2] += qv.z; qs[3] += qv.w;
            kb[0] |= (uint32_t)(kv.x & 1) << d;
            kb[1] |= (uint32_t)(kv.y & 1) << d;
            kb[2] |= (uint32_t)(kv.z & 1) << d;
            kb[3] |= (uint32_t)(kv.w & 1) << d;
        }
    }
#pragma unroll
    for (int t = 0; t < 4; t++) {
        s_qs[dg][hw][t] = qs[t];
        s_kb[dg][hw][t] = kb[t];
    }
    __syncthreads();

    if (dg == 0 && act) {
        float va = 0.f;
#pragma unroll
        for (int t = 0; t < 4; t++) {
            float q = (float)(qs[t] + s_qs[1][hw][t] + s_qs[2][hw][t] + s_qs[3][hw][t]);
            uint32_t m0 = kb[t] | (s_kb[1][hw][t] << 12);
            uint32_t m1 = s_kb[2][hw][t] | (s_kb[3][hw][t] << 12);
            float h = va + (q - va) * 0.5f;
            bool s  = (h - 0.5f) >= 0.0f;
            va = s ? 0.f : h;
            s_m[hw][t][0] = s ? m0 : 0u;
            s_m[hw][t][1] = s ? m1 : 0u;
        }
    }
    __syncthreads();

    const int tidl = dg * 224 + hw;
#pragma unroll 1
    for (int l = tidl; l < HW * 4 * 6; l += 896) {
        int g  = l % 6;
        int r  = l / 6;
        int whw = r % HW;
        int t   = r / HW;
        uint32_t mask = s_m[whw][t][g >= 3 ? 1 : 0];
        uint32_t bits = mask >> ((g >= 3 ? g - 3 : g) * 8);
        uint4 v;
        v.x = pk2h(bits);
        v.y = pk2h(bits >> 2);
        v.z = pk2h(bits >> 4);
        v.w = pk2h(bits >> 6);
        size_t n = (size_t)(b * HW + whw) * 4 + t;
        uint4* dst = reinterpret_cast<uint4*>(g_yhf + n * CH + head * DH);
        dst[g] = v;
    }
}

// ===========================================================================
// proj GEMM: 2-term fp16 split + fused final LIF, 2-stage cp.async pipeline.
// Dynamic smem: 2 stages x 3 planes x [128][40] fp16 = 60 KB + colOff.
// ===========================================================================
#define PJ_PLANES   3
#define PJ_STAGE_B  (PJ_PLANES * 128 * PITCH * 2)       // 30720
#define PJ_DSMEM    (2 * PJ_STAGE_B + 512)              // 61952

__global__ void __launch_bounds__(256, 2) proj_mma_kernel(
    const float* __restrict__ gamma, const float* __restrict__ beta,
    const float* __restrict__ mean,  const float* __restrict__ var,
    const float* __restrict__ bias,  float* __restrict__ out)
{
    extern __shared__ char dsm[];
    __half* sP = reinterpret_cast<__half*>(dsm);
    int* colOff = reinterpret_cast<int*>(dsm + 2 * PJ_STAGE_B);
    // plane index: 0,1 = A(pw0,pw1); 2 = B(y)
#define PSP(S, P, R, C) sP[(((S) * PJ_PLANES + (P)) * 128 + (R)) * PITCH + (C)]

    const int tid  = threadIdx.x;
    const int wid  = tid >> 5;
    const int lane = tid & 31;
    const int mbase = blockIdx.y * 128;
    const int nbase = blockIdx.x * 128;

    if (tid < 128) colOff[tid] = proj_col_offset(nbase + tid);

    const int wm = (wid & 3) * 32;
    const int wn = (wid >> 2) * 64;

    const int a_r  = (lane & 7) + ((lane >> 3) & 1) * 8;
    const int a_kc = (lane >> 4) * 8;
    const int b_r  = (lane & 7) + (lane >> 4) * 8;
    const int b_kc = ((lane >> 3) & 1) * 8;

    const __half* gsrc[PJ_PLANES] = {
        g_pw0 + (size_t)mbase * CH, g_pw1 + (size_t)mbase * CH,
        g_yhf + (size_t)nbase * CH };

    const int l_row = tid >> 2;
    const int l_q   = (tid & 3) * 8;

#define PJ_LOAD(KC_)                                                            \
    do {                                                                        \
        int s_ = (KC_) & 1;                                                     \
        int ko_ = (KC_) * KC + l_q;                                             \
        _Pragma("unroll")                                                       \
        for (int r2 = 0; r2 < 2; r2++) {                                        \
            int row_ = l_row + r2 * 64;                                         \
            _Pragma("unroll")                                                   \
            for (int p = 0; p < PJ_PLANES; p++)                                 \
                CPASYNC16(smem_u32(&PSP(s_, p, row_, l_q)),                     \
                          gsrc[p] + (size_t)row_ * CH + ko_);                   \
        }                                                                       \
        CP_COMMIT();                                                            \
    } while (0)

    float acc[2][8][4];
#pragma unroll
    for (int mt = 0; mt < 2; mt++)
#pragma unroll
        for (int nt = 0; nt < 8; nt++)
#pragma unroll
            for (int r = 0; r < 4; r++) acc[mt][nt][r] = 0.f;

    PJ_LOAD(0);

#pragma unroll 1
    for (int kc = 0; kc < CH / KC; kc++) {
        CP_WAIT_ALL();
        __syncthreads();
        if (kc + 1 < CH / KC) PJ_LOAD(kc + 1);

        const int s = kc & 1;
#pragma unroll
        for (int kk = 0; kk < 2; kk++) {
            const int k0 = kk * 16;
            uint32_t a[2][2][4];
#pragma unroll
            for (int p = 0; p < 2; p++)
#pragma unroll
                for (int mt = 0; mt < 2; mt++) {
                    uint32_t ad = smem_u32(&PSP(s, p, wm + mt * 16 + a_r, k0 + a_kc));
                    LDMX4(a[p][mt][0], a[p][mt][1], a[p][mt][2], a[p][mt][3], ad);
                }
#pragma unroll
            for (int nt2 = 0; nt2 < 4; nt2++) {
                uint32_t b0, b1, b2, b3;
                uint32_t bd = smem_u32(&PSP(s, 2, wn + nt2 * 16 + b_r, k0 + b_kc));
                LDMX4(b0, b1, b2, b3, bd);
#pragma unroll
                for (int p = 0; p < 2; p++)
#pragma unroll
                    for (int mt = 0; mt < 2; mt++) {
                        MMA16816(acc[mt][nt2 * 2],
                                 a[p][mt][0], a[p][mt][1], a[p][mt][2], a[p][mt][3],
                                 b0, b1);
                        MMA16816(acc[mt][nt2 * 2 + 1],
                                 a[p][mt][0], a[p][mt][1], a[p][mt][2], a[p][mt][3],
                                 b2, b3);
                    }
            }
        }
    }
#undef PJ_LOAD

    // Epilogue 1: bias + BN -> fused LIF -> spike bytes (sbuf aliases stages)
    __syncthreads();
    unsigned char (*sbuf)[132] = reinterpret_cast<unsigned char(*)[132]>(dsm);
#pragma unroll
    for (int mt = 0; mt < 2; mt++) {
        int ma = wm + mt * 16 + (lane >> 2);
        int mb = ma + 8;
        int oa = mbase + ma, ob = mbase + mb;
        float inva = gamma[oa] / sqrtf(var[oa] + 1e-5f);
        float sha  = beta[oa] - mean[oa] * inva;
        float bva  = bias[oa];
        float invb = gamma[ob] / sqrtf(var[ob] + 1e-5f);
        float shb  = beta[ob] - mean[ob] * invb;
        float bvb  = bias[ob];
#pragma unroll
        for (int nt = 0; nt < 8; nt++) {
            int n = wn + nt * 8 + (lane & 3) * 2;
            const float* c = acc[mt][nt];
            float za0 = (c[0] + bva) * inva + sha;
            float za1 = (c[1] + bva) * inva + sha;
            float zb0 = (c[2] + bvb) * invb + shb;
            float zb1 = (c[3] + bvb) * invb + shb;
            float sa0, sa1, sb0, sb1;
            lif_pair(lane, za0, za1, sa0, sa1);
            lif_pair(lane, zb0, zb1, sb0, sb1);
            sbuf[n][ma]     = (unsigned char)(sa0 != 0.f);
            sbuf[n + 1][ma] = (unsigned char)(sa1 != 0.f);
            sbuf[n][mb]     = (unsigned char)(sb0 != 0.f);
            sbuf[n + 1][mb] = (unsigned char)(sb1 != 0.f);
        }
    }
    __syncthreads();

    // Epilogue 2: coalesced plane-major fp32 spike stores
    {
        const int p = tid & 31;
        const int g = tid >> 5;
#pragma unroll 1
        for (int i = 0; i < 64; i++) {
            int mt_ = g * 64 + i;
            int m = mt_ >> 2;
            int t = mt_ & 3;
            int nloc = p * 4 + t;
            float s = (float)sbuf[nloc][m];
            out[colOff[nloc] + (mbase + m) * HW] = s;
        }
    }
#undef PSP
}

// ===========================================================================
extern "C" void kernel_launch(void* const* d_in, const int* in_sizes, int n_in,
                              void* d_out, int out_size)
{
    const float* x          = (const float*)d_in[0];
    const float* q_w        = (const float*)d_in[1];
    const float* q_gamma    = (const float*)d_in[2];
    const float* q_beta     = (const float*)d_in[3];
    const float* q_mean     = (const float*)d_in[4];
    const float* q_var      = (const float*)d_in[5];
    const float* k_w        = (const float*)d_in[6];
    const float* k_gamma    = (const float*)d_in[7];
    const float* k_beta     = (const float*)d_in[8];
    const float* k_mean     = (const float*)d_in[9];
    const float* k_var      = (const float*)d_in[10];
    const float* proj_w     = (const float*)d_in[11];
    const float* proj_b     = (const float*)d_in[12];
    const float* proj_gamma = (const float*)d_in[13];
    const float* proj_beta  = (const float*)d_in[14];
    const float* proj_mean  = (const float*)d_in[15];
    const float* proj_var   = (const float*)d_in[16];

    cudaFuncSetAttribute(qk_mma_kernel,
                         cudaFuncAttributeMaxDynamicSharedMemorySize, QK_DSMEM);
    cudaFuncSetAttribute(proj_mma_kernel,
                         cudaFuncAttributeMaxDynamicSharedMemorySize, PJ_DSMEM);

    __half *qw0, *qw1, *kw0, *kw1;
    cudaGetSymbolAddress((void**)&qw0, g_qw0);
    cudaGetSymbolAddress((void**)&qw1, g_qw1);
    cudaGetSymbolAddress((void**)&kw0, g_kw0);
    cudaGetSymbolAddress((void**)&kw1, g_kw1);
    unsigned char *qsp, *ksp;
    cudaGetSymbolAddress((void**)&qsp, g_qsp);
    cudaGetSymbolAddress((void**)&ksp, g_ksp);

    dim3 ggrid(NTOT / 128, CH / 128);   // (196, 3)
    int wblocks = (CH * CH + 255) / 256;

    wsplit_all_kernel<<<dim3(wblocks, 3), 256>>>(q_w, k_w, proj_w);
    xsplit_kernel<<<dim3(T_STEPS * BATCH, CH / 32), dim3(32, 8)>>>(x);
    qk_mma_kernel<<<ggrid, 256, QK_DSMEM>>>(qw0, qw1, q_gamma, q_beta,
                                            q_mean, q_var, qsp);
    qk_mma_kernel<<<ggrid, 256, QK_DSMEM>>>(kw0, kw1, k_gamma, k_beta,
                                            k_mean, k_var, ksp);
    lif_attn_kernel<<<BATCH * HEADS, dim3(224, 4)>>>();
    proj_mma_kernel<<<ggrid, 256, PJ_DSMEM>>>(proj_gamma, proj_beta,
                                              proj_mean, proj_var, proj_b,
                                              (float*)d_out);
}

// round 17
// speedup vs baseline: 1.2488x; 1.0188x over previous
#include <cuda_runtime.h>
#include <cuda_fp16.h>
#include <cstdint>

// Problem constants
#define T_STEPS 4
#define BATCH   32
#define CH      384
#define HW      196
#define HEADS   8
#define DH      48
#define CHW     (CH*HW)          // 75264
#define BCHW    (BATCH*CHW)      // 2408448
#define TOTAL   (T_STEPS*BCHW)   // 9633792
#define NTOT    (T_STEPS*BATCH*HW) // 25088 (= 196 * 128 exactly)

// Scratch (static device globals -- allocation-guard safe)
__device__ unsigned char g_qsp[TOTAL];  // q spikes, [b][c][hw] x uchar4(t)
__device__ unsigned char g_ksp[TOTAL];  // k spikes, same layout
__device__ __half g_yhf[TOTAL];    // proj input, [n][c] row-major (n permuted), 0/1
__device__ __half g_pw0[CH*CH];    // proj_w 2-way fp16 split
__device__ __half g_pw1[CH*CH];
__device__ __half g_qw0[CH*CH];    // q_w split
__device__ __half g_qw1[CH*CH];
__device__ __half g_kw0[CH*CH];    // k_w split
__device__ __half g_kw1[CH*CH];
__device__ __half g_x0[TOTAL];     // X 2-way fp16 split, [n][k], n=(b*HW+hw)*4+t
__device__ __half g_x1[TOTAL];

// GEMM column permutation: n = (b*HW + hw)*4 + t
__device__ __forceinline__ int proj_col_offset(int n) {
    int t   = n & 3;
    int bhw = n >> 2;
    int b   = bhw / HW;
    int hw  = bhw - b * HW;
    return t * BCHW + b * CHW + hw;     // element offset without channel term
}

__device__ __forceinline__ uint32_t smem_u32(const void* p) {
    uint32_t a;
    asm("{ .reg .u64 t; cvta.to.shared.u64 t, %1; cvt.u32.u64 %0, t; }"
        : "=r"(a) : "l"(p));
    return a;
}

#define MMA16816(CP, A0, A1, A2, A3, B0, B1)                                    \
    asm volatile(                                                               \
        "mma.sync.aligned.m16n8k16.row.col.f32.f16.f16.f32 "                    \
        "{%0,%1,%2,%3}, {%4,%5,%6,%7}, {%8,%9}, {%0,%1,%2,%3};"                 \
        : "+f"((CP)[0]), "+f"((CP)[1]), "+f"((CP)[2]), "+f"((CP)[3])            \
        : "r"(A0), "r"(A1), "r"(A2), "r"(A3), "r"(B0), "r"(B1))

#define LDMX4(R0, R1, R2, R3, AD)                                               \
    asm volatile("ldmatrix.sync.aligned.m8n8.x4.shared.b16 {%0,%1,%2,%3}, [%4];"\
        : "=r"(R0), "=r"(R1), "=r"(R2), "=r"(R3) : "r"(AD))

#define CPASYNC16(DST, SRC)                                                     \
    asm volatile("cp.async.cg.shared.global [%0], [%1], 16;"                    \
        :: "r"(DST), "l"(SRC) : "memory")
#define CP_COMMIT()   asm volatile("cp.async.commit_group;" ::: "memory")
#define CP_WAIT_ALL() asm volatile("cp.async.wait_group 0;" ::: "memory")

// Fused LIF over a lane pair (proven R12-R15): even lane (t0,t1), odd (t2,t3).
__device__ __forceinline__ void lif_pair(int lane, float z0, float z1,
                                         float& s0, float& s1)
{
    float h0 = z0 * 0.5f;
    bool  a0 = h0 >= 1.0f;
    float v  = a0 ? 0.f : h0;
    float h1 = v + (z1 - v) * 0.5f;
    bool  a1 = h1 >= 1.0f;
    float v1 = a1 ? 0.f : h1;
    float vin = __shfl_xor_sync(0xffffffffu, v1, 1);
    if (lane & 1) {
        h0 = vin + (z0 - vin) * 0.5f;
        a0 = h0 >= 1.0f;
        v  = a0 ? 0.f : h0;
        h1 = v + (z1 - v) * 0.5f;
        a1 = h1 >= 1.0f;
    }
    s0 = a0 ? 1.f : 0.f;
    s1 = a1 ? 1.f : 0.f;
}

// ===========================================================================
// Merged prep: X transpose+split AND all 3 weight splits in ONE launch.
// blocks [0, 1536): xsplit (tb, cgroup); blocks [1536, 3264): weight split.
// ===========================================================================
#define XBLOCKS (T_STEPS * BATCH * (CH / 32))   // 1536
#define WBLK1   ((CH * CH) / 256)               // 576
#define PREP_BLOCKS (XBLOCKS + 3 * WBLK1)       // 3264

__global__ void __launch_bounds__(256) prep_kernel(
    const float* __restrict__ X,
    const float* __restrict__ qw, const float* __restrict__ kw,
    const float* __restrict__ pw)
{
    const int bid = blockIdx.x;
    const int tid = threadIdx.x;

    if (bid >= XBLOCKS) {
        // ---- weight 2-way fp16 split ----
        int widx = bid - XBLOCKS;
        int sel  = widx / WBLK1;
        int i    = (widx - sel * WBLK1) * 256 + tid;
        const float* src = (sel == 0) ? qw : (sel == 1) ? kw : pw;
        __half* d0 = (sel == 0) ? g_qw0 : (sel == 1) ? g_kw0 : g_pw0;
        __half* d1 = (sel == 0) ? g_qw1 : (sel == 1) ? g_kw1 : g_pw1;
        float v = src[i];
        __half h0 = __float2half_rn(v);
        __half h1 = __float2half_rn(v - __half2float(h0));
        d0[i] = h0; d1[i] = h1;
        return;
    }

    // ---- X transpose + split:  X[t][b][c][hw] -> planes[(b*HW+hw)*4+t][c] ----
    __shared__ float tile[32][33];
    const int tb = bid / (CH / 32);
    const int t  = tb >> 5;
    const int b  = tb & 31;
    const int c0 = (bid % (CH / 32)) * 32;
    const int tx = tid & 31;
    const int ty = tid >> 5;     // 0..7

#pragma unroll 1
    for (int hw0 = 0; hw0 < HW; hw0 += 32) {
        __syncthreads();
#pragma unroll
        for (int i = 0; i < 4; i++) {
            int c  = c0 + ty + i * 8;
            int hw = hw0 + tx;
            tile[ty + i * 8][tx] = (hw < HW) ? X[tb * CHW + c * HW + hw] : 0.f;
        }
        __syncthreads();
#pragma unroll
        for (int i = 0; i < 4; i++) {
            int hw = hw0 + ty + i * 8;
            if (hw < HW) {
                float v = tile[tx][ty + i * 8];
                __half h0 = __float2half_rn(v);
                __half h1 = __float2half_rn(v - __half2float(h0));
                size_t o = ((size_t)(b * HW + hw) * 4 + t) * CH + c0 + tx;
                g_x0[o] = h0; g_x1[o] = h1;
            }
        }
    }
}

// ===========================================================================
// MERGED Q+K GEMM: 3-term fp16-split mma + fused LIF + spike-byte output.
// grid (196, 6): blockIdx.y in [0,3) = q tiles, [3,6) = k tiles.
// 2-stage cp.async pipeline, KC=32, PITCH=40 (proven R15 body).
// ===========================================================================
#define KC      32
#define PITCH   40
#define QK_PLANES   4
#define QK_STAGE_B  (QK_PLANES * 128 * PITCH * 2)       // 40960
#define QK_DSMEM    (2 * QK_STAGE_B)                    // 81920

__global__ void __launch_bounds__(256, 2) qk_mma_kernel(
    const float* __restrict__ q_gamma, const float* __restrict__ q_beta,
    const float* __restrict__ q_mean,  const float* __restrict__ q_var,
    const float* __restrict__ k_gamma, const float* __restrict__ k_beta,
    const float* __restrict__ k_mean,  const float* __restrict__ k_var)
{
    extern __shared__ char dsm[];
    __half* sP = reinterpret_cast<__half*>(dsm);
#define QSP(S, P, R, C) sP[(((S) * QK_PLANES + (P)) * 128 + (R)) * PITCH + (C)]

    const int tid  = threadIdx.x;
    const int wid  = tid >> 5;
    const int lane = tid & 31;
    const bool is_k = blockIdx.y >= 3;
    const int mbase = (is_k ? (blockIdx.y - 3) : blockIdx.y) * 128;
    const int nbase = blockIdx.x * 128;

    const __half* w0 = is_k ? g_kw0 : g_qw0;
    const __half* w1 = is_k ? g_kw1 : g_qw1;
    const float* gamma = is_k ? k_gamma : q_gamma;
    const float* beta  = is_k ? k_beta  : q_beta;
    const float* mean  = is_k ? k_mean  : q_mean;
    const float* var   = is_k ? k_var   : q_var;
    unsigned char* out = is_k ? g_ksp : g_qsp;

    const int wm = (wid & 3) * 32;
    const int wn = (wid >> 2) * 64;

    const int a_r  = (lane & 7) + ((lane >> 3) & 1) * 8;
    const int a_kc = (lane >> 4) * 8;
    const int b_r  = (lane & 7) + (lane >> 4) * 8;
    const int b_kc = ((lane >> 3) & 1) * 8;

    const __half* gsrc[QK_PLANES] = {
        w0 + (size_t)mbase * CH, w1 + (size_t)mbase * CH,
        g_x0 + (size_t)nbase * CH, g_x1 + (size_t)nbase * CH };

    const int l_row = tid >> 2;          // 0..63 (+64 second pass)
    const int l_q   = (tid & 3) * 8;

#define QK_LOAD(KC_)                                                            \
    do {                                                                        \
        int s_ = (KC_) & 1;                                                     \
        int ko_ = (KC_) * KC + l_q;                                             \
        _Pragma("unroll")                                                       \
        for (int r2 = 0; r2 < 2; r2++) {                                        \
            int row_ = l_row + r2 * 64;                                         \
            _Pragma("unroll")                                                   \
            for (int p = 0; p < QK_PLANES; p++)                                 \
                CPASYNC16(smem_u32(&QSP(s_, p, row_, l_q)),                     \
                          gsrc[p] + (size_t)row_ * CH + ko_);                   \
        }                                                                       \
        CP_COMMIT();                                                            \
    } while (0)

    float acc[2][8][4];
#pragma unroll
    for (int mt = 0; mt < 2; mt++)
#pragma unroll
        for (int nt = 0; nt < 8; nt++)
#pragma unroll
            for (int r = 0; r < 4; r++) acc[mt][nt][r] = 0.f;

    QK_LOAD(0);

#pragma unroll 1
    for (int kc = 0; kc < CH / KC; kc++) {
        CP_WAIT_ALL();
        __syncthreads();
        if (kc + 1 < CH / KC) QK_LOAD(kc + 1);

        const int s = kc & 1;
#pragma unroll
        for (int kk = 0; kk < 2; kk++) {
            const int k0 = kk * 16;
            uint32_t a[2][2][4];
#pragma unroll
            for (int p = 0; p < 2; p++)
#pragma unroll
                for (int mt = 0; mt < 2; mt++) {
                    uint32_t ad = smem_u32(&QSP(s, p, wm + mt * 16 + a_r, k0 + a_kc));
                    LDMX4(a[p][mt][0], a[p][mt][1], a[p][mt][2], a[p][mt][3], ad);
                }
#pragma unroll
            for (int nt2 = 0; nt2 < 4; nt2++) {
                uint32_t b[2][4];
#pragma unroll
                for (int p = 0; p < 2; p++) {
                    uint32_t bd = smem_u32(&QSP(s, p + 2, wn + nt2 * 16 + b_r, k0 + b_kc));
                    LDMX4(b[p][0], b[p][1], b[p][2], b[p][3], bd);
                }
#define QK_PAIR(I, J)                                                           \
                _Pragma("unroll")                                               \
                for (int mt = 0; mt < 2; mt++) {                                \
                    MMA16816(acc[mt][nt2 * 2],                                  \
                             a[I][mt][0], a[I][mt][1], a[I][mt][2], a[I][mt][3],\
                             b[J][0], b[J][1]);                                 \
                    MMA16816(acc[mt][nt2 * 2 + 1],                              \
                             a[I][mt][0], a[I][mt][1], a[I][mt][2], a[I][mt][3],\
                             b[J][2], b[J][3]);                                 \
                }
                QK_PAIR(0, 0)
                QK_PAIR(1, 0)
                QK_PAIR(0, 1)
#undef QK_PAIR
            }
        }
    }
#undef QK_LOAD

    // Epilogue 1: BN -> fused LIF -> spike bytes into sbuf (aliases stages)
    __syncthreads();
    unsigned char (*sbuf)[132] = reinterpret_cast<unsigned char(*)[132]>(dsm);
#pragma unroll
    for (int mt = 0; mt < 2; mt++) {
        int ma = wm + mt * 16 + (lane >> 2);
        int mb = ma + 8;
        int oa = mbase + ma, ob = mbase + mb;
        float inva = gamma[oa] / sqrtf(var[oa] + 1e-5f);
        float sha  = beta[oa] - mean[oa] * inva;
        float invb = gamma[ob] / sqrtf(var[ob] + 1e-5f);
        float shb  = beta[ob] - mean[ob] * invb;
#pragma unroll
        for (int nt = 0; nt < 8; nt++) {
            int n = wn + nt * 8 + (lane & 3) * 2;
            const float* c = acc[mt][nt];
            float za0 = c[0] * inva + sha;
            float za1 = c[1] * inva + sha;
            float zb0 = c[2] * invb + shb;
            float zb1 = c[3] * invb + shb;
            float sa0, sa1, sb0, sb1;
            lif_pair(lane, za0, za1, sa0, sa1);
            lif_pair(lane, zb0, zb1, sb0, sb1);
            sbuf[n][ma]     = (unsigned char)(sa0 != 0.f);
            sbuf[n + 1][ma] = (unsigned char)(sa1 != 0.f);
            sbuf[n][mb]     = (unsigned char)(sb0 != 0.f);
            sbuf[n + 1][mb] = (unsigned char)(sb1 != 0.f);
        }
    }
    __syncthreads();

    // Epilogue 2: coalesced uchar4 stores
    {
        const int p  = tid & 31;
        const int g  = tid >> 5;
        int pix = (nbase >> 2) + p;
        int b   = pix / HW;
        int hw  = pix - b * HW;
        int pb  = b * CHW + hw;
#pragma unroll 1
        for (int i = 0; i < 16; i++) {
            int m = g * 16 + i;
            uchar4 v;
            v.x = sbuf[p * 4 + 0][m];
            v.y = sbuf[p * 4 + 1][m];
            v.z = sbuf[p * 4 + 2][m];
            v.w = sbuf[p * 4 + 3][m];
            *reinterpret_cast<uchar4*>(out + (size_t)(pb + (mbase + m) * HW) * 4) = v;
        }
    }
#undef QSP
}

// ===========================================================================
// Attention gate (R14/R15 form): spike bytes in, gated y (fp16, permuted) out
// ===========================================================================
__device__ __forceinline__ uint32_t pk2h(uint32_t m) {
    return ((m & 1u) ? 0x3C00u : 0u) | ((m & 2u) ? 0x3C000000u : 0u);
}

__global__ void __launch_bounds__(896) lif_attn_kernel()
{
    __shared__ int      s_qs[4][224][4];
    __shared__ uint32_t s_kb[4][224][4];
    __shared__ uint32_t s_m[224][4][2];

    const int bh   = blockIdx.x;
    const int b    = bh >> 3;
    const int head = bh & 7;
    const int hw   = threadIdx.x;
    const int dg   = threadIdx.y;
    const bool act = hw < HW;

    const int cb = head * DH + dg * 12;

    int      qs[4] = {0, 0, 0, 0};
    uint32_t kb[4] = {0u, 0u, 0u, 0u};

    if (act) {
        const uchar4* q4 = reinterpret_cast<const uchar4*>(g_qsp);
        const uchar4* k4 = reinterpret_cast<const uchar4*>(g_ksp);
#pragma unroll
        for (int d = 0; d < 12; d++) {
            int ci = b * CHW + (cb + d) * HW + hw;
            uchar4 qv = q4[ci];
            uchar4 kv = k4[ci];
            qs[0] += qv.x; qs[1] += qv.y; qs[2] += qv.z; qs[3] += qv.w;
            kb[0] |= (uint32_t)(kv.x & 1) << d;
            kb[1] |= (uint32_t)(kv.y & 1) << d;
            kb[2] |= (uint32_t)(kv.z & 1) << d;
            kb[3] |= (uint32_t)(kv.w & 1) << d;
        }
    }
#pragma unroll
    for (int t = 0; t < 4; t++) {
        s_qs[dg][hw][t] = qs[t];
        s_kb[dg][hw][t] = kb[t];
    }
    __syncthreads();

    if (dg == 0 && act) {
        float va = 0.f;
#pragma unroll
        for (int t = 0; t < 4; t++) {
            float q = (float)(qs[t] + s_qs[1][hw][t] + s_qs[2][hw][t] + s_qs[3][hw][t]);
            uint32_t m0 = kb[t] | (s_kb[1][hw][t] << 12);
            uint32_t m1 = s_kb[2][hw][t] | (s_kb[3][hw][t] << 12);
            float h = va + (q - va) * 0.5f;
            bool s  = (h - 0.5f) >= 0.0f;
            va = s ? 0.f : h;
            s_m[hw][t][0] = s ? m0 : 0u;
            s_m[hw][t][1] = s ? m1 : 0u;
        }
    }
    __syncthreads();

    const int tidl = dg * 224 + hw;
#pragma unroll 1
    for (int l = tidl; l < HW * 4 * 6; l += 896) {
        int g  = l % 6;
        int r  = l / 6;
        int whw = r % HW;
        int t   = r / HW;
        uint32_t mask = s_m[whw][t][g >= 3 ? 1 : 0];
        uint32_t bits = mask >> ((g >= 3 ? g - 3 : g) * 8);
        uint4 v;
        v.x = pk2h(bits);
        v.y = pk2h(bits >> 2);
        v.z = pk2h(bits >> 4);
        v.w = pk2h(bits >> 6);
        size_t n = (size_t)(b * HW + whw) * 4 + t;
        uint4* dst = reinterpret_cast<uint4*>(g_yhf + n * CH + head * DH);
        dst[g] = v;
    }
}

// ===========================================================================
// proj GEMM: 2-term fp16 split + fused final LIF, 2-stage cp.async pipeline
// (proven R15 body).
// ===========================================================================
#define PJ_PLANES   3
#define PJ_STAGE_B  (PJ_PLANES * 128 * PITCH * 2)       // 30720
#define PJ_DSMEM    (2 * PJ_STAGE_B + 512)              // 61952

__global__ void __launch_bounds__(256, 2) proj_mma_kernel(
    const float* __restrict__ gamma, const float* __restrict__ beta,
    const float* __restrict__ mean,  const float* __restrict__ var,
    const float* __restrict__ bias,  float* __restrict__ out)
{
    extern __shared__ char dsm[];
    __half* sP = reinterpret_cast<__half*>(dsm);
    int* colOff = reinterpret_cast<int*>(dsm + 2 * PJ_STAGE_B);
#define PSP(S, P, R, C) sP[(((S) * PJ_PLANES + (P)) * 128 + (R)) * PITCH + (C)]

    const int tid  = threadIdx.x;
    const int wid  = tid >> 5;
    const int lane = tid & 31;
    const int mbase = blockIdx.y * 128;
    const int nbase = blockIdx.x * 128;

    if (tid < 128) colOff[tid] = proj_col_offset(nbase + tid);

    const int wm = (wid & 3) * 32;
    const int wn = (wid >> 2) * 64;

    const int a_r  = (lane & 7) + ((lane >> 3) & 1) * 8;
    const int a_kc = (lane >> 4) * 8;
    const int b_r  = (lane & 7) + (lane >> 4) * 8;
    const int b_kc = ((lane >> 3) & 1) * 8;

    const __half* gsrc[PJ_PLANES] = {
        g_pw0 + (size_t)mbase * CH, g_pw1 + (size_t)mbase * CH,
        g_yhf + (size_t)nbase * CH };

    const int l_row = tid >> 2;
    const int l_q   = (tid & 3) * 8;

#define PJ_LOAD(KC_)                                                            \
    do {                                                                        \
        int s_ = (KC_) & 1;                                                     \
        int ko_ = (KC_) * KC + l_q;                                             \
        _Pragma("unroll")                                                       \
        for (int r2 = 0; r2 < 2; r2++) {                                        \
            int row_ = l_row + r2 * 64;                                         \
            _Pragma("unroll")                                                   \
            for (int p = 0; p < PJ_PLANES; p++)                                 \
                CPASYNC16(smem_u32(&PSP(s_, p, row_, l_q)),                     \
                          gsrc[p] + (size_t)row_ * CH + ko_);                   \
        }                                                                       \
        CP_COMMIT();                                                            \
    } while (0)

    float acc[2][8][4];
#pragma unroll
    for (int mt = 0; mt < 2; mt++)
#pragma unroll
        for (int nt = 0; nt < 8; nt++)
#pragma unroll
            for (int r = 0; r < 4; r++) acc[mt][nt][r] = 0.f;

    PJ_LOAD(0);

#pragma unroll 1
    for (int kc = 0; kc < CH / KC; kc++) {
        CP_WAIT_ALL();
        __syncthreads();
        if (kc + 1 < CH / KC) PJ_LOAD(kc + 1);

        const int s = kc & 1;
#pragma unroll
        for (int kk = 0; kk < 2; kk++) {
            const int k0 = kk * 16;
            uint32_t a[2][2][4];
#pragma unroll
            for (int p = 0; p < 2; p++)
#pragma unroll
                for (int mt = 0; mt < 2; mt++) {
                    uint32_t ad = smem_u32(&PSP(s, p, wm + mt * 16 + a_r, k0 + a_kc));
                    LDMX4(a[p][mt][0], a[p][mt][1], a[p][mt][2], a[p][mt][3], ad);
                }
#pragma unroll
            for (int nt2 = 0; nt2 < 4; nt2++) {
                uint32_t b0, b1, b2, b3;
                uint32_t bd = smem_u32(&PSP(s, 2, wn + nt2 * 16 + b_r, k0 + b_kc));
                LDMX4(b0, b1, b2, b3, bd);
#pragma unroll
                for (int p = 0; p < 2; p++)
#pragma unroll
                    for (int mt = 0; mt < 2; mt++) {
                        MMA16816(acc[mt][nt2 * 2],
                                 a[p][mt][0], a[p][mt][1], a[p][mt][2], a[p][mt][3],
                                 b0, b1);
                        MMA16816(acc[mt][nt2 * 2 + 1],
                                 a[p][mt][0], a[p][mt][1], a[p][mt][2], a[p][mt][3],
                                 b2, b3);
                    }
            }
        }
    }
#undef PJ_LOAD

    // Epilogue 1: bias + BN -> fused LIF -> spike bytes (sbuf aliases stages)
    __syncthreads();
    unsigned char (*sbuf)[132] = reinterpret_cast<unsigned char(*)[132]>(dsm);
#pragma unroll
    for (int mt = 0; mt < 2; mt++) {
        int ma = wm + mt * 16 + (lane >> 2);
        int mb = ma + 8;
        int oa = mbase + ma, ob = mbase + mb;
        float inva = gamma[oa] / sqrtf(var[oa] + 1e-5f);
        float sha  = beta[oa] - mean[oa] * inva;
        float bva  = bias[oa];
        float invb = gamma[ob] / sqrtf(var[ob] + 1e-5f);
        float shb  = beta[ob] - mean[ob] * invb;
        float bvb  = bias[ob];
#pragma unroll
        for (int nt = 0; nt < 8; nt++) {
            int n = wn + nt * 8 + (lane & 3) * 2;
            const float* c = acc[mt][nt];
            float za0 = (c[0] + bva) * inva + sha;
            float za1 = (c[1] + bva) * inva + sha;
            float zb0 = (c[2] + bvb) * invb + shb;
            float zb1 = (c[3] + bvb) * invb + shb;
            float sa0, sa1, sb0, sb1;
            lif_pair(lane, za0, za1, sa0, sa1);
            lif_pair(lane, zb0, zb1, sb0, sb1);
            sbuf[n][ma]     = (unsigned char)(sa0 != 0.f);
            sbuf[n + 1][ma] = (unsigned char)(sa1 != 0.f);
            sbuf[n][mb]     = (unsigned char)(sb0 != 0.f);
            sbuf[n + 1][mb] = (unsigned char)(sb1 != 0.f);
        }
    }
    __syncthreads();

    // Epilogue 2: coalesced plane-major fp32 spike stores
    {
        const int p = tid & 31;
        const int g = tid >> 5;
#pragma unroll 1
        for (int i = 0; i < 64; i++) {
            int mt_ = g * 64 + i;
            int m = mt_ >> 2;
            int t = mt_ & 3;
            int nloc = p * 4 + t;
            float s = (float)sbuf[nloc][m];
            out[colOff[nloc] + (mbase + m) * HW] = s;
        }
    }
#undef PSP
}

// ===========================================================================
extern "C" void kernel_launch(void* const* d_in, const int* in_sizes, int n_in,
                              void* d_out, int out_size)
{
    const float* x          = (const float*)d_in[0];
    const float* q_w        = (const float*)d_in[1];
    const float* q_gamma    = (const float*)d_in[2];
    const float* q_beta     = (const float*)d_in[3];
    const float* q_mean     = (const float*)d_in[4];
    const float* q_var      = (const float*)d_in[5];
    const float* k_w        = (const float*)d_in[6];
    const float* k_gamma    = (const float*)d_in[7];
    const float* k_beta     = (const float*)d_in[8];
    const float* k_mean     = (const float*)d_in[9];
    const float* k_var      = (const float*)d_in[10];
    const float* proj_w     = (const float*)d_in[11];
    const float* proj_b     = (const float*)d_in[12];
    const float* proj_gamma = (const float*)d_in[13];
    const float* proj_beta  = (const float*)d_in[14];
    const float* proj_mean  = (const float*)d_in[15];
    const float* proj_var   = (const float*)d_in[16];

    cudaFuncSetAttribute(qk_mma_kernel,
                         cudaFuncAttributeMaxDynamicSharedMemorySize, QK_DSMEM);
    cudaFuncSetAttribute(proj_mma_kernel,
                         cudaFuncAttributeMaxDynamicSharedMemorySize, PJ_DSMEM);

    dim3 qkgrid(NTOT / 128, 6);         // (196, 6): y<3 = q, y>=3 = k
    dim3 pjgrid(NTOT / 128, CH / 128);  // (196, 3)

    prep_kernel<<<PREP_BLOCKS, 256>>>(x, q_w, k_w, proj_w);
    qk_mma_kernel<<<qkgrid, 256, QK_DSMEM>>>(q_gamma, q_beta, q_mean, q_var,
                                             k_gamma, k_beta, k_mean, k_var);
    lif_attn_kernel<<<BATCH * HEADS, dim3(224, 4)>>>();
    proj_mma_kernel<<<pjgrid, 256, PJ_DSMEM>>>(proj_gamma, proj_beta,
                                               proj_mean, proj_var, proj_b,
                                               (float*)d_out);
}